// round 10
// baseline (speedup 1.0000x reference)
#include <cuda_runtime.h>
#include <cuda_bf16.h>
#include <math.h>
#include <stdint.h>

// ---------------------------------------------------------------------------
// GuidedUpsampleUnitGF — conv1/conv2/conv3 via mma.sync bf16 (3-term split)
// NOTE: __device__ globals must NEVER be passed as kernel args from host
//       (host sees shadow symbol -> ATS-readable zeros). Select in device code.
// ---------------------------------------------------------------------------

#define P2    65536
#define C_IN  263
#define CE    256
#define EPS_GF 0.01f

// padded activation planes for conv2: [split 2][py 260][px 264][ch 256] bf16
#define PADH 260
#define PADW 264
#define PADP (PADH * PADW)
#define HPLANE ((size_t)PADP * 256)

#define WT_ELEMS (2 * 25 * 256 * 256)

#define K1PAD 320
#define UPLANE ((size_t)P2 * K1PAD)
#define VPLANE ((size_t)P2 * 256)

#define STAGE_BYTES 65536
#define SMEM_1X1 (3 * STAGE_BYTES)

// conv2 smem: A ring 3 x 32KB, B ring 2 x 33792 (132 rows x 128B x hi/lo)
#define C2_A_STAGE 32768
#define C2_B_OFF   98304
#define C2_B_SLOT  33792
#define C2_B_SPLIT 16896
#define SMEM_C2    (C2_B_OFF + 2 * C2_B_SLOT)   // 165888

// -------------------- scratch ----------------------------------------------
__device__ __align__(256) float g_Ct[(size_t)P2 * 256]; // px-major conv2 out
__device__ __align__(256) float g_Aa[(size_t)P2 * 256]; // 'a' of guided filter
__device__ __align__(256) float g_F [(size_t)P2 * 256]; // 'b' of guided filter
__device__ __align__(256) float g_guide[P2];
__device__ __align__(256) float g_meanI[P2];
__device__ __align__(256) float g_varI[P2];
__device__ __align__(256) __nv_bfloat16 g_H [2 * HPLANE];     // conv1 out hi/lo padded
__device__ __align__(256) __nv_bfloat16 g_Wt[WT_ELEMS];       // conv2 W hi/lo
__device__ __align__(256) __nv_bfloat16 g_U [2 * UPLANE];     // conv1 input px-major hi/lo
__device__ __align__(256) __nv_bfloat16 g_V [2 * VPLANE];     // conv3 input hi/lo (filt)
__device__ __align__(256) __nv_bfloat16 g_W1[2 * 256 * K1PAD];
__device__ __align__(256) __nv_bfloat16 g_W3[2 * 256 * 256];

// -------------------- helpers ----------------------------------------------
__device__ __forceinline__ uint32_t smem_u32(const void* p) {
    uint32_t a;
    asm("{ .reg .u64 t; cvta.to.shared.u64 t, %1; cvt.u32.u64 %0, t; }" : "=r"(a) : "l"(p));
    return a;
}
__device__ __forceinline__ void cpa16(uint32_t dst, const void* src) {
    asm volatile("cp.async.cg.shared.global [%0], [%1], 16;\n" :: "r"(dst), "l"(src));
}
__device__ __forceinline__ void ldsm4(uint32_t* r, uint32_t addr) {
    asm volatile("ldmatrix.sync.aligned.m8n8.x4.shared.b16 {%0,%1,%2,%3}, [%4];"
                 : "=r"(r[0]), "=r"(r[1]), "=r"(r[2]), "=r"(r[3]) : "r"(addr));
}
__device__ __forceinline__ void mma_bf16(float* d, const uint32_t* a,
                                         uint32_t b0, uint32_t b1) {
    asm volatile("mma.sync.aligned.m16n8k16.row.col.f32.bf16.bf16.f32 "
                 "{%0,%1,%2,%3}, {%4,%5,%6,%7}, {%8,%9}, {%0,%1,%2,%3};"
                 : "+f"(d[0]), "+f"(d[1]), "+f"(d[2]), "+f"(d[3])
                 : "r"(a[0]), "r"(a[1]), "r"(a[2]), "r"(a[3]), "r"(b0), "r"(b1));
}

// -------------------- fused upsample + transpose + split -> g_U -------------
// grid (P2/32, K1PAD/32), block (32, 8)
__global__ void __launch_bounds__(256) k_upT(const float* __restrict__ fg,
                                             const float* __restrict__ bg,
                                             const float* __restrict__ mask,
                                             const float* __restrict__ feat)
{
    __shared__ float tile[32][33];
    const int p0 = blockIdx.x * 32;
    const int c0 = blockIdx.y * 32;
    const int tx = threadIdx.x, ty = threadIdx.y;

    // bilinear geometry for pixel p0+tx (shared by all channels)
    int p = p0 + tx;
    int y = p >> 8, x = p & 255;
    float sy = 0.5f * (float)y - 0.25f;
    float sx = 0.5f * (float)x - 0.25f;
    float fy = sy - floorf(sy);
    float fx = sx - floorf(sx);
    int y0 = (int)floorf(sy);
    int x0 = (int)floorf(sx);
    int y0c = max(y0, 0),       x0c = max(x0, 0);
    int y1c = min(y0 + 1, 127), x1c = min(x0 + 1, 127);
    int i00 = y0c * 128 + x0c, i01 = y0c * 128 + x1c;
    int i10 = y1c * 128 + x0c, i11 = y1c * 128 + x1c;
    float w00 = (1.f - fy) * (1.f - fx), w01 = (1.f - fy) * fx;
    float w10 = fy * (1.f - fx),         w11 = fy * fx;

#pragma unroll
    for (int k = 0; k < 4; k++) {
        int ch = c0 + ty + k * 8;
        float v = 0.f;
        if (ch < C_IN) {
            const float* src;
            if (ch == 0)      src = mask;
            else if (ch <= 3) src = fg + (ch - 1) * 16384;
            else if (ch <= 6) src = bg + (ch - 4) * 16384;
            else              src = feat + (ch - 7) * 16384;
            v = w00 * src[i00] + w01 * src[i01] + w10 * src[i10] + w11 * src[i11];
        }
        tile[ty + k * 8][tx] = v;
    }
    __syncthreads();
#pragma unroll
    for (int k = 0; k < 4; k++) {
        int pp = p0 + ty + k * 8;
        int ch = c0 + tx;
        float v = tile[tx][ty + k * 8];
        __nv_bfloat16 hi = __float2bfloat16(v);
        g_U[(size_t)pp * K1PAD + ch] = hi;
        g_U[UPLANE + (size_t)pp * K1PAD + ch] = __float2bfloat16(v - __bfloat162float(hi));
    }
}

// guide from g_U (hi+lo reconstruct, channels 1..3 = fg)
__global__ void k_guide()
{
    int p = blockIdx.x * blockDim.x + threadIdx.x;
    if (p >= P2) return;
    float s = 0.f;
#pragma unroll
    for (int c = 1; c <= 3; c++) {
        s += __bfloat162float(g_U[(size_t)p * K1PAD + c])
           + __bfloat162float(g_U[UPLANE + (size_t)p * K1PAD + c]);
    }
    g_guide[p] = s * (128.0f / 3.0f);
}

__device__ __forceinline__ int cnt_axis(int i)
{
    return min(i + 2, 255) - max(i - 2, 0) + 1;
}

__global__ void k_istats()
{
    int p = blockIdx.x * blockDim.x + threadIdx.x;
    if (p >= P2) return;
    int y = p >> 8, x = p & 255;
    float sI = 0.f, sI2 = 0.f;
    for (int dy = -2; dy <= 2; dy++) {
        int yy = y + dy;
        if (yy < 0 || yy > 255) continue;
        for (int dx = -2; dx <= 2; dx++) {
            int xx = x + dx;
            if (xx < 0 || xx > 255) continue;
            float v = g_guide[yy * 256 + xx];
            sI += v; sI2 += v * v;
        }
    }
    float inv = 1.f / (float)(cnt_axis(y) * cnt_axis(x));
    float mI = sI * inv;
    g_meanI[p] = mI;
    g_varI[p]  = sI2 * inv - mI * mI;
}

// -------------------- weight prep kernels ----------------------------------
// conv2 weights: g_Wt[s][tap][m][ch]
__global__ void k_prepw(const float* __restrict__ w2)
{
    int idx = blockIdx.x * blockDim.x + threadIdx.x;
    if (idx >= WT_ELEMS) return;
    int ch = idx & 255;
    int m  = (idx >> 8) & 255;
    int st = idx >> 16;
    int tap = st % 25;
    int s   = st / 25;
    float w = w2[(size_t)m * 6400 + ch * 25 + tap];
    __nv_bfloat16 hi = __float2bfloat16(w);
    g_Wt[idx] = s ? __float2bfloat16(w - __bfloat162float(hi)) : hi;
}

// conv1 weights: g_W1[s][m][320] (zero-pad ch >= 263)
__global__ void k_prepw1(const float* __restrict__ w1)
{
    int idx = blockIdx.x * blockDim.x + threadIdx.x;
    if (idx >= 2 * 256 * K1PAD) return;
    int ch = idx % K1PAD;
    int m  = (idx / K1PAD) & 255;
    int s  = idx / (K1PAD * 256);
    float w = (ch < C_IN) ? w1[(size_t)m * C_IN + ch] : 0.f;
    __nv_bfloat16 hi = __float2bfloat16(w);
    g_W1[idx] = s ? __float2bfloat16(w - __bfloat162float(hi)) : hi;
}

// conv3 weights: g_W3[s][m][256]
__global__ void k_prepw3(const float* __restrict__ w3)
{
    int idx = blockIdx.x * blockDim.x + threadIdx.x;
    if (idx >= 2 * 256 * 256) return;
    int ch = idx & 255;
    int m  = (idx >> 8) & 255;
    int s  = idx >> 16;
    float w = w3[(size_t)m * 256 + ch];
    __nv_bfloat16 hi = __float2bfloat16(w);
    g_W3[idx] = s ? __float2bfloat16(w - __bfloat162float(hi)) : hi;
}

// -------------------- generic 1x1 conv MMA kernel --------------------------
// MODE 0: A=g_W1, B=g_U, epilogue -> g_H bf16 hi/lo padded px-major (conv1)
// MODE 1: A=g_W3, B=g_V, epilogue -> Out fp32 ch-major (conv3)
template<int NKC, int MODE>
__global__ void __launch_bounds__(256, 1) k_mma1x1(const float* __restrict__ bias,
                                                   float* __restrict__ Out)
{
    constexpr int KPAD = NKC * 64;
    constexpr long APLANE_B = (long)256 * KPAD * 2;
    constexpr long BPLANE_B = (long)P2 * KPAD * 2;

    extern __shared__ __align__(1024) char smem[];
    uint32_t sb = smem_u32(smem);
    const int tid = threadIdx.x;
    const int lane = tid & 31, wid = tid >> 5;
    const int wm = wid >> 1, wn = wid & 1;
    const int n0 = blockIdx.x * 128;
    const int m0 = blockIdx.y * 128;

    const int rb = tid >> 3;
    const int cc = tid & 7;
    // device-side symbol references (NOT kernel args!)
    const char* AB = (MODE == 0) ? (const char*)g_W1 : (const char*)g_W3;
    const char* BB = (MODE == 0) ? (const char*)g_U  : (const char*)g_V;

    uint32_t aRow[2], aSw[2];
    const uint32_t aHi = lane >> 4;
#pragma unroll
    for (int f = 0; f < 2; f++) {
        int r = wm * 32 + f * 16 + (lane & 15);
        aRow[f] = r << 7;
        aSw[f] = r & 7;
    }
    uint32_t bRow[4], bSw[4];
    const uint32_t bHi = (lane >> 3) & 1;
#pragma unroll
    for (int g = 0; g < 4; g++) {
        int r = wn * 64 + g * 16 + (lane & 7) + ((lane >> 4) << 3);
        bRow[g] = r << 7;
        bSw[g] = r & 7;
    }

    float acc[2][8][4];
#pragma unroll
    for (int i = 0; i < 2; i++)
#pragma unroll
        for (int j = 0; j < 8; j++)
#pragma unroll
            for (int e = 0; e < 4; e++) acc[i][j][e] = 0.f;

    auto fill = [&](int it) {
        uint32_t stg = sb + (it % 3) * STAGE_BYTES;
        long kO = (long)it * 128;   // 64 ch * 2B
#pragma unroll
        for (int t = 0; t < 4; t++) {
            int r = rb + 32 * t;
            uint32_t sw = (uint32_t)((cc ^ (r & 7)) << 4);
            long a0 = (long)(m0 + r) * (KPAD * 2) + kO + cc * 16;
            cpa16(stg + r * 128 + sw,         AB + a0);
            cpa16(stg + 16384 + r * 128 + sw, AB + a0 + APLANE_B);
            long b0 = (long)(n0 + r) * (KPAD * 2) + kO + cc * 16;
            cpa16(stg + 32768 + r * 128 + sw, BB + b0);
            cpa16(stg + 49152 + r * 128 + sw, BB + b0 + BPLANE_B);
        }
        asm volatile("cp.async.commit_group;" ::: "memory");
    };

    fill(0);
    fill(1);

    for (int it = 0; it < NKC; it++) {
        if (it == NKC - 1) asm volatile("cp.async.wait_group 0;" ::: "memory");
        else               asm volatile("cp.async.wait_group 1;" ::: "memory");
        __syncthreads();
        uint32_t stg = sb + (it % 3) * STAGE_BYTES;
#pragma unroll
        for (int ks = 0; ks < 4; ks++) {
            uint32_t Wh[2][4], Wl[2][4], Bh[4][4], Bl[4][4];
#pragma unroll
            for (int f = 0; f < 2; f++) {
                uint32_t col = ((((uint32_t)(ks << 1) + aHi) ^ aSw[f]) << 4);
                ldsm4(Wh[f], stg + aRow[f] + col);
                ldsm4(Wl[f], stg + 16384 + aRow[f] + col);
            }
#pragma unroll
            for (int g = 0; g < 4; g++) {
                uint32_t col = ((((uint32_t)(ks << 1) + bHi) ^ bSw[g]) << 4);
                ldsm4(Bh[g], stg + 32768 + bRow[g] + col);
                ldsm4(Bl[g], stg + 49152 + bRow[g] + col);
            }
#pragma unroll
            for (int f = 0; f < 2; f++)
#pragma unroll
                for (int g = 0; g < 4; g++)
#pragma unroll
                    for (int h = 0; h < 2; h++) {
                        float* d = acc[f][g * 2 + h];
                        mma_bf16(d, Wh[f], Bh[g][h * 2], Bh[g][h * 2 + 1]);
                        mma_bf16(d, Wh[f], Bl[g][h * 2], Bl[g][h * 2 + 1]);
                        mma_bf16(d, Wl[f], Bh[g][h * 2], Bh[g][h * 2 + 1]);
                    }
        }
        if (it + 2 < NKC) fill(it + 2);
    }
    __syncthreads();

    // ---- staged epilogue ----
    const int l4 = lane >> 2, l2 = (lane & 3) * 2;
    if (MODE == 0) {
        uint32_t* sU = (uint32_t*)smem;   // [n 128][pitch 130] packed (hi,lo)
#pragma unroll
        for (int f = 0; f < 2; f++) {
            int mb = wm * 32 + f * 16 + l4;
            float b0v = bias[m0 + mb], b1v = bias[m0 + mb + 8];
#pragma unroll
            for (int j = 0; j < 8; j++) {
                int nl = wn * 64 + j * 8 + l2;
#pragma unroll
                for (int e = 0; e < 4; e++) {
                    float v = acc[f][j][e] + ((e & 2) ? b1v : b0v);
                    v = fmaxf(v, 0.f);
                    __nv_bfloat16 hi = __float2bfloat16(v);
                    __nv_bfloat16 lo = __float2bfloat16(v - __bfloat162float(hi));
                    uint32_t u = (uint32_t)__bfloat16_as_ushort(hi)
                               | ((uint32_t)__bfloat16_as_ushort(lo) << 16);
                    sU[(nl + (e & 1)) * 130 + mb + ((e & 2) ? 8 : 0)] = u;
                }
            }
        }
        __syncthreads();
#pragma unroll 8
        for (int t = 0; t < 64; t++) {
            int idx = tid + t * 256;
            int row = idx >> 7, ml = idx & 127;
            uint32_t u = sU[row * 130 + ml];
            int ng = n0 + row;
            size_t pixpad = (size_t)(((ng >> 8) + 2) * PADW + (ng & 255) + 2) * 256 + m0 + ml;
            g_H[pixpad] = __ushort_as_bfloat16((unsigned short)(u & 0xFFFF));
            g_H[HPLANE + pixpad] = __ushort_as_bfloat16((unsigned short)(u >> 16));
        }
    } else {
        float* sF = (float*)smem;   // [m 128][pitch 130]
#pragma unroll
        for (int f = 0; f < 2; f++) {
            int mb = wm * 32 + f * 16 + l4;
            float b0v = bias[m0 + mb], b1v = bias[m0 + mb + 8];
#pragma unroll
            for (int j = 0; j < 8; j++) {
                int nl = wn * 64 + j * 8 + l2;
#pragma unroll
                for (int e = 0; e < 4; e++) {
                    float v = acc[f][j][e] + ((e & 2) ? b1v : b0v);
                    sF[(mb + ((e & 2) ? 8 : 0)) * 130 + nl + (e & 1)] = fmaxf(v, 0.f);
                }
            }
        }
        __syncthreads();
#pragma unroll 8
        for (int t = 0; t < 64; t++) {
            int idx = tid + t * 256;
            int ml = idx >> 7, nl = idx & 127;
            Out[(size_t)(m0 + ml) * P2 + n0 + nl] = sF[ml * 130 + nl];
        }
    }
}

// -------------------- conv2: mma.sync bf16, B reused across dx -------------
// loop order: it = (dy*4 + chunk)*5 + dx ; B tile (132 halo rows) per (dy,chunk)
__global__ void __launch_bounds__(256, 1) k_conv2mma(const float* __restrict__ bias2)
{
    extern __shared__ __align__(1024) char smem[];
    uint32_t sb = smem_u32(smem);
    const int tid = threadIdx.x;
    const int lane = tid & 31, wid = tid >> 5;
    const int wm = wid >> 1, wn = wid & 1;
    const int bx = blockIdx.x;
    const int y = bx >> 1, x0 = (bx & 1) * 128;
    const int m0 = blockIdx.y * 128;
    const int pixbase = y * 256 + x0;

    const int rb = tid >> 3;
    const int cc = tid & 7;
    const char* WtB = (const char*)g_Wt;
    const char* HB  = (const char*)g_H;

    uint32_t aRow[2], aSw[2];
    const uint32_t aHi = lane >> 4;
#pragma unroll
    for (int f = 0; f < 2; f++) {
        int r = wm * 32 + f * 16 + (lane & 15);
        aRow[f] = r << 7;
        aSw[f] = r & 7;
    }
    uint32_t rB0[4];
    const uint32_t bHi = (lane >> 3) & 1;
#pragma unroll
    for (int g = 0; g < 4; g++)
        rB0[g] = wn * 64 + g * 16 + (lane & 7) + ((lane >> 4) << 3);

    float acc[2][8][4];
#pragma unroll
    for (int i = 0; i < 2; i++)
#pragma unroll
        for (int j = 0; j < 8; j++)
#pragma unroll
            for (int e = 0; e < 4; e++) acc[i][j][e] = 0.f;

    auto fill = [&](int it) {
        int dy = it / 20, rem = it % 20, chunk = rem / 5, dx = rem % 5;
        int tap = dy * 5 + dx;
        const char* srcA = WtB + (long)tap * 131072 + chunk * 128;
        uint32_t stgA = sb + (it % 3) * C2_A_STAGE;
#pragma unroll
        for (int t = 0; t < 4; t++) {
            int r = rb + 32 * t;
            uint32_t sw = (uint32_t)((cc ^ (r & 7)) << 4);
            long a0 = (long)(m0 + r) * 512 + cc * 16;
            cpa16(stgA + r * 128 + sw,         srcA + a0);
            cpa16(stgA + 16384 + r * 128 + sw, srcA + a0 + 3276800);
        }
        if (dx == 0) {
            uint32_t stgB = sb + C2_B_OFF + ((it / 5) & 1) * C2_B_SLOT;
            const char* srcB = HB + (long)((y + dy) * PADW + x0) * 512 + chunk * 128;
            for (int o = tid * 16; o < C2_B_SPLIT; o += 4096) {
                int r = o >> 7;
                int cB = o & 127;
                uint32_t sw = (uint32_t)(r * 128 + (cB ^ ((r & 7) << 4)));
                cpa16(stgB + sw,              srcB + (long)r * 512 + cB);
                cpa16(stgB + C2_B_SPLIT + sw, srcB + (long)r * 512 + cB + (long)HPLANE * 2);
            }
        }
        asm volatile("cp.async.commit_group;" ::: "memory");
    };

    fill(0);
    fill(1);

    for (int it = 0; it < 100; it++) {
        if (it == 99) asm volatile("cp.async.wait_group 0;" ::: "memory");
        else          asm volatile("cp.async.wait_group 1;" ::: "memory");
        __syncthreads();
        const int dxi = it % 5;
        uint32_t stgA = sb + (it % 3) * C2_A_STAGE;
        uint32_t stgB = sb + C2_B_OFF + ((it / 5) & 1) * C2_B_SLOT;
#pragma unroll
        for (int ks = 0; ks < 4; ks++) {
            uint32_t Wh[2][4], Wl[2][4], Bh[4][4], Bl[4][4];
#pragma unroll
            for (int f = 0; f < 2; f++) {
                uint32_t col = ((((uint32_t)(ks << 1) + aHi) ^ aSw[f]) << 4);
                ldsm4(Wh[f], stgA + aRow[f] + col);
                ldsm4(Wl[f], stgA + 16384 + aRow[f] + col);
            }
#pragma unroll
            for (int g = 0; g < 4; g++) {
                uint32_t rr = rB0[g] + dxi;
                uint32_t addr = stgB + (rr << 7)
                              + ((((uint32_t)(ks << 1) + bHi) ^ (rr & 7)) << 4);
                ldsm4(Bh[g], addr);
                ldsm4(Bl[g], addr + C2_B_SPLIT);
            }
#pragma unroll
            for (int f = 0; f < 2; f++)
#pragma unroll
                for (int g = 0; g < 4; g++)
#pragma unroll
                    for (int h = 0; h < 2; h++) {
                        float* d = acc[f][g * 2 + h];
                        mma_bf16(d, Wh[f], Bh[g][h * 2], Bh[g][h * 2 + 1]);
                        mma_bf16(d, Wh[f], Bl[g][h * 2], Bl[g][h * 2 + 1]);
                        mma_bf16(d, Wl[f], Bh[g][h * 2], Bh[g][h * 2 + 1]);
                    }
        }
        if (it + 2 < 100) fill(it + 2);
    }
    __syncthreads();

    // staged epilogue -> g_Ct px-major, coalesced
    const int l4 = lane >> 2, l2 = (lane & 3) * 2;
    float* sF = (float*)smem;   // [n 128][pitch 130]
#pragma unroll
    for (int f = 0; f < 2; f++) {
        int mb = wm * 32 + f * 16 + l4;
        float b0v = bias2[m0 + mb], b1v = bias2[m0 + mb + 8];
#pragma unroll
        for (int j = 0; j < 8; j++) {
            int nl = wn * 64 + j * 8 + l2;
#pragma unroll
            for (int e = 0; e < 4; e++) {
                float v = acc[f][j][e] + ((e & 2) ? b1v : b0v);
                sF[(nl + (e & 1)) * 130 + mb + ((e & 2) ? 8 : 0)] = fmaxf(v, 0.f);
            }
        }
    }
    __syncthreads();
#pragma unroll 8
    for (int t = 0; t < 64; t++) {
        int idx = tid + t * 256;
        int row = idx >> 7, ml = idx & 127;
        g_Ct[(size_t)(pixbase + row) * 256 + m0 + ml] = sF[row * 130 + ml];
    }
}

// -------------------- fused guided filter (direct stencil, y-strip) --------
// Pass A: g_Ct -> a (g_Aa), b (g_F). One thread = 8-y strip at fixed (x, ch).
// grid (256 x, 32 ystrips), block 256 (= channels). No smem, no syncs.
__global__ void __launch_bounds__(256) k_gfA()
{
    const int c = threadIdx.x;
    const int x = blockIdx.x;
    const int ys = blockIdx.y * 8;
    const int xlo = max(x - 2, 0), xhi = min(x + 2, 255);

    float rp[12], rip[12];
#pragma unroll
    for (int j = 0; j < 12; j++) {
        int row = ys - 2 + j;
        float sp = 0.f, sip = 0.f;
        if ((unsigned)row < 256u) {
            size_t rowbase = (size_t)row * 65536 + c;
            for (int xx = xlo; xx <= xhi; xx++) {
                float pv = g_Ct[rowbase + (size_t)xx * 256];
                sp  += pv;
                sip += pv * g_guide[row * 256 + xx];
            }
        }
        rp[j] = sp; rip[j] = sip;
    }
    const float cw = (float)(xhi - xlo + 1);
#pragma unroll
    for (int k = 0; k < 8; k++) {
        int yo = ys + k;
        float sp = 0.f, sip = 0.f;
#pragma unroll
        for (int j = 0; j < 5; j++) { sp += rp[k + j]; sip += rip[k + j]; }
        float inv = 1.f / ((float)cnt_axis(yo) * cw);
        float mp  = sp * inv;
        float mIp = sip * inv;
        int ppix = yo * 256 + x;
        float mI = g_meanI[ppix];
        float a = (mIp - mI * mp) / (g_varI[ppix] + EPS_GF);
        size_t o = (size_t)ppix * 256 + c;
        g_Aa[o] = a;
        g_F[o]  = mp - a * mI;
    }
}

// Pass B: mean(a)*I + mean(b) -> g_V bf16 hi/lo (conv3 input)
__global__ void __launch_bounds__(256) k_gfB()
{
    const int c = threadIdx.x;
    const int x = blockIdx.x;
    const int ys = blockIdx.y * 8;
    const int xlo = max(x - 2, 0), xhi = min(x + 2, 255);

    float ra[12], rb[12];
#pragma unroll
    for (int j = 0; j < 12; j++) {
        int row = ys - 2 + j;
        float s1 = 0.f, s2 = 0.f;
        if ((unsigned)row < 256u) {
            size_t rowbase = (size_t)row * 65536 + c;
            for (int xx = xlo; xx <= xhi; xx++) {
                s1 += g_Aa[rowbase + (size_t)xx * 256];
                s2 += g_F [rowbase + (size_t)xx * 256];
            }
        }
        ra[j] = s1; rb[j] = s2;
    }
    const float cw = (float)(xhi - xlo + 1);
#pragma unroll
    for (int k = 0; k < 8; k++) {
        int yo = ys + k;
        float s1 = 0.f, s2 = 0.f;
#pragma unroll
        for (int j = 0; j < 5; j++) { s1 += ra[k + j]; s2 += rb[k + j]; }
        float inv = 1.f / ((float)cnt_axis(yo) * cw);
        int ppix = yo * 256 + x;
        float filt = (s1 * inv) * g_guide[ppix] + s2 * inv;
        __nv_bfloat16 fh = __float2bfloat16(filt);
        size_t o = (size_t)ppix * 256 + c;
        g_V[o] = fh;
        g_V[VPLANE + o] = __float2bfloat16(filt - __bfloat162float(fh));
    }
}

// -------------------- mask head --------------------------------------------
__global__ void k_maskhead(const float* __restrict__ featOut,
                           const float* __restrict__ wm,
                           const float* __restrict__ bm,
                           float* __restrict__ maskOut)
{
    __shared__ float sw[256];
    int tid = threadIdx.x;
    sw[tid] = wm[tid];
    __syncthreads();
    int p = blockIdx.x * blockDim.x + tid;
    if (p >= P2) return;
    float s = bm[0];
#pragma unroll 8
    for (int c = 0; c < 256; c++)
        s += sw[c] * featOut[(size_t)c * P2 + p];
    maskOut[p] = 1.f / (1.f + expf(-s));
}

// ---------------------------------------------------------------------------
extern "C" void kernel_launch(void* const* d_in, const int* in_sizes, int n_in,
                              void* d_out, int out_size)
{
    const float* fg   = (const float*)d_in[0];
    const float* bg   = (const float*)d_in[1];
    const float* mask = (const float*)d_in[2];
    const float* feat = (const float*)d_in[3];
    const float* w1   = (const float*)d_in[4];
    const float* b1   = (const float*)d_in[5];
    const float* w2   = (const float*)d_in[6];
    const float* b2   = (const float*)d_in[7];
    const float* w3   = (const float*)d_in[8];
    const float* b3   = (const float*)d_in[9];
    const float* wm   = (const float*)d_in[10];
    const float* bm   = (const float*)d_in[11];

    float* out     = (float*)d_out;
    float* maskOut = out;           // (1,1,256,256)
    float* featOut = out + P2;      // (1,256,256,256)

    const int T = 256;

    cudaFuncSetAttribute(k_conv2mma,
                         cudaFuncAttributeMaxDynamicSharedMemorySize, SMEM_C2);
    cudaFuncSetAttribute(k_mma1x1<5, 0>,
                         cudaFuncAttributeMaxDynamicSharedMemorySize, SMEM_1X1);
    cudaFuncSetAttribute(k_mma1x1<4, 1>,
                         cudaFuncAttributeMaxDynamicSharedMemorySize, SMEM_1X1);

    // weight preps (no deps)
    k_prepw <<<(WT_ELEMS + T - 1) / T, T>>>(w2);
    k_prepw1<<<(2 * 256 * K1PAD + T - 1) / T, T>>>(w1);
    k_prepw3<<<(2 * 256 * 256 + T - 1) / T, T>>>(w3);
    // 1. fused upsample + transpose + bf16 split -> g_U
    k_upT<<<dim3(P2 / 32, K1PAD / 32), dim3(32, 8)>>>(fg, bg, mask, feat);
    // 2. guide (from g_U) + box statistics
    k_guide <<<(P2 + T - 1) / T, T>>>();
    k_istats<<<(P2 + T - 1) / T, T>>>();
    // 3. conv1 mma -> g_H
    k_mma1x1<5, 0><<<dim3(512, 2), 256, SMEM_1X1>>>(b1, nullptr);
    // 4. conv2 mma -> g_Ct
    k_conv2mma<<<dim3(512, 2), 256, SMEM_C2>>>(b2);
    // 5. guided filter: two direct-stencil passes (no D/E intermediates)
    k_gfA<<<dim3(256, 32), 256>>>();
    k_gfB<<<dim3(256, 32), 256>>>();
    // 6. conv3 mma -> featOut
    k_mma1x1<4, 1><<<dim3(512, 2), 256, SMEM_1X1>>>(b3, featOut);
    // 7. mask head
    k_maskhead<<<(P2 + T - 1) / T, T>>>(featOut, wm, bm, maskOut);
}

// round 11
// speedup vs baseline: 1.2965x; 1.2965x over previous
#include <cuda_runtime.h>
#include <cuda_bf16.h>
#include <cuda_fp16.h>
#include <math.h>
#include <stdint.h>

// ---------------------------------------------------------------------------
// GuidedUpsampleUnitGF
//   conv1: bf16 3-term mma  -> g_H (fp16 single plane, padded px-major)
//   conv2: fp16 2-term mma  (W hi/lo fp16, activations single fp16)
//   conv3: bf16 3-term mma
// NOTE: __device__ globals must NEVER be passed as kernel args from host.
// ---------------------------------------------------------------------------

#define P2    65536
#define C_IN  263
#define CE    256
#define EPS_GF 0.01f

#define PADH 260
#define PADW 264
#define PADP (PADH * PADW)
#define HPLANE ((size_t)PADP * 256)

#define WT_ELEMS (2 * 25 * 256 * 256)

#define K1PAD 320
#define UPLANE ((size_t)P2 * K1PAD)
#define VPLANE ((size_t)P2 * 256)

#define STAGE_BYTES 65536
#define SMEM_1X1 (3 * STAGE_BYTES)

// conv2 smem: A ring 3 x 32KB (Wh/Wl fp16), B ring 2 x 16896 (132 rows x 128B)
#define C2_A_STAGE 32768
#define C2_B_OFF   98304
#define C2_B_SLOT  16896
#define SMEM_C2    (C2_B_OFF + 2 * C2_B_SLOT)   // 132096

// -------------------- scratch ----------------------------------------------
__device__ __align__(256) float g_Ct[(size_t)P2 * 256]; // px-major conv2 out
__device__ __align__(256) float g_Aa[(size_t)P2 * 256]; // 'a' of guided filter
__device__ __align__(256) float g_D [(size_t)P2 * 256];
__device__ __align__(256) float g_E [(size_t)P2 * 256];
__device__ __align__(256) float g_F [(size_t)P2 * 256]; // 'b' of guided filter
__device__ __align__(256) float g_guide[P2];
__device__ __align__(256) float g_meanI[P2];
__device__ __align__(256) float g_varI[P2];
__device__ __align__(256) unsigned short g_H[HPLANE];         // conv1 out fp16, padded
__device__ __align__(256) __half g_Wt[WT_ELEMS];              // conv2 W fp16 hi/lo
__device__ __align__(256) __nv_bfloat16 g_U [2 * UPLANE];     // conv1 input hi/lo
__device__ __align__(256) __nv_bfloat16 g_V [2 * VPLANE];     // conv3 input hi/lo
__device__ __align__(256) __nv_bfloat16 g_W1[2 * 256 * K1PAD];
__device__ __align__(256) __nv_bfloat16 g_W3[2 * 256 * 256];

// -------------------- helpers ----------------------------------------------
__device__ __forceinline__ uint32_t smem_u32(const void* p) {
    uint32_t a;
    asm("{ .reg .u64 t; cvta.to.shared.u64 t, %1; cvt.u32.u64 %0, t; }" : "=r"(a) : "l"(p));
    return a;
}
__device__ __forceinline__ void cpa16(uint32_t dst, const void* src) {
    asm volatile("cp.async.cg.shared.global [%0], [%1], 16;\n" :: "r"(dst), "l"(src));
}
__device__ __forceinline__ void ldsm4(uint32_t* r, uint32_t addr) {
    asm volatile("ldmatrix.sync.aligned.m8n8.x4.shared.b16 {%0,%1,%2,%3}, [%4];"
                 : "=r"(r[0]), "=r"(r[1]), "=r"(r[2]), "=r"(r[3]) : "r"(addr));
}
__device__ __forceinline__ void mma_bf16(float* d, const uint32_t* a,
                                         uint32_t b0, uint32_t b1) {
    asm volatile("mma.sync.aligned.m16n8k16.row.col.f32.bf16.bf16.f32 "
                 "{%0,%1,%2,%3}, {%4,%5,%6,%7}, {%8,%9}, {%0,%1,%2,%3};"
                 : "+f"(d[0]), "+f"(d[1]), "+f"(d[2]), "+f"(d[3])
                 : "r"(a[0]), "r"(a[1]), "r"(a[2]), "r"(a[3]), "r"(b0), "r"(b1));
}
__device__ __forceinline__ void mma_f16(float* d, const uint32_t* a,
                                        uint32_t b0, uint32_t b1) {
    asm volatile("mma.sync.aligned.m16n8k16.row.col.f32.f16.f16.f32 "
                 "{%0,%1,%2,%3}, {%4,%5,%6,%7}, {%8,%9}, {%0,%1,%2,%3};"
                 : "+f"(d[0]), "+f"(d[1]), "+f"(d[2]), "+f"(d[3])
                 : "r"(a[0]), "r"(a[1]), "r"(a[2]), "r"(a[3]), "r"(b0), "r"(b1));
}

// -------------------- fused upsample + transpose + split -> g_U -------------
__global__ void __launch_bounds__(256) k_upT(const float* __restrict__ fg,
                                             const float* __restrict__ bg,
                                             const float* __restrict__ mask,
                                             const float* __restrict__ feat)
{
    __shared__ float tile[32][33];
    const int p0 = blockIdx.x * 32;
    const int c0 = blockIdx.y * 32;
    const int tx = threadIdx.x, ty = threadIdx.y;

    int p = p0 + tx;
    int y = p >> 8, x = p & 255;
    float sy = 0.5f * (float)y - 0.25f;
    float sx = 0.5f * (float)x - 0.25f;
    float fy = sy - floorf(sy);
    float fx = sx - floorf(sx);
    int y0 = (int)floorf(sy);
    int x0 = (int)floorf(sx);
    int y0c = max(y0, 0),       x0c = max(x0, 0);
    int y1c = min(y0 + 1, 127), x1c = min(x0 + 1, 127);
    int i00 = y0c * 128 + x0c, i01 = y0c * 128 + x1c;
    int i10 = y1c * 128 + x0c, i11 = y1c * 128 + x1c;
    float w00 = (1.f - fy) * (1.f - fx), w01 = (1.f - fy) * fx;
    float w10 = fy * (1.f - fx),         w11 = fy * fx;

#pragma unroll
    for (int k = 0; k < 4; k++) {
        int ch = c0 + ty + k * 8;
        float v = 0.f;
        if (ch < C_IN) {
            const float* src;
            if (ch == 0)      src = mask;
            else if (ch <= 3) src = fg + (ch - 1) * 16384;
            else if (ch <= 6) src = bg + (ch - 4) * 16384;
            else              src = feat + (ch - 7) * 16384;
            v = w00 * src[i00] + w01 * src[i01] + w10 * src[i10] + w11 * src[i11];
        }
        tile[ty + k * 8][tx] = v;
    }
    __syncthreads();
#pragma unroll
    for (int k = 0; k < 4; k++) {
        int pp = p0 + ty + k * 8;
        int ch = c0 + tx;
        float v = tile[tx][ty + k * 8];
        __nv_bfloat16 hi = __float2bfloat16(v);
        g_U[(size_t)pp * K1PAD + ch] = hi;
        g_U[UPLANE + (size_t)pp * K1PAD + ch] = __float2bfloat16(v - __bfloat162float(hi));
    }
}

// guide from g_U (hi+lo reconstruct, channels 1..3 = fg)
__global__ void k_guide()
{
    int p = blockIdx.x * blockDim.x + threadIdx.x;
    if (p >= P2) return;
    float s = 0.f;
#pragma unroll
    for (int c = 1; c <= 3; c++) {
        s += __bfloat162float(g_U[(size_t)p * K1PAD + c])
           + __bfloat162float(g_U[UPLANE + (size_t)p * K1PAD + c]);
    }
    g_guide[p] = s * (128.0f / 3.0f);
}

__device__ __forceinline__ int cnt_axis(int i)
{
    return min(i + 2, 255) - max(i - 2, 0) + 1;
}

__global__ void k_istats()
{
    int p = blockIdx.x * blockDim.x + threadIdx.x;
    if (p >= P2) return;
    int y = p >> 8, x = p & 255;
    float sI = 0.f, sI2 = 0.f;
    for (int dy = -2; dy <= 2; dy++) {
        int yy = y + dy;
        if (yy < 0 || yy > 255) continue;
        for (int dx = -2; dx <= 2; dx++) {
            int xx = x + dx;
            if (xx < 0 || xx > 255) continue;
            float v = g_guide[yy * 256 + xx];
            sI += v; sI2 += v * v;
        }
    }
    float inv = 1.f / (float)(cnt_axis(y) * cnt_axis(x));
    float mI = sI * inv;
    g_meanI[p] = mI;
    g_varI[p]  = sI2 * inv - mI * mI;
}

// -------------------- weight prep kernels ----------------------------------
// conv2 weights fp16 hi/lo: g_Wt[s][tap][m][ch]
__global__ void k_prepw(const float* __restrict__ w2)
{
    int idx = blockIdx.x * blockDim.x + threadIdx.x;
    if (idx >= WT_ELEMS) return;
    int ch = idx & 255;
    int m  = (idx >> 8) & 255;
    int st = idx >> 16;
    int tap = st % 25;
    int s   = st / 25;
    float w = w2[(size_t)m * 6400 + ch * 25 + tap];
    __half hi = __float2half(w);
    g_Wt[idx] = s ? __float2half(w - __half2float(hi)) : hi;
}

// conv1 weights: g_W1[s][m][320] (zero-pad ch >= 263), bf16 hi/lo
__global__ void k_prepw1(const float* __restrict__ w1)
{
    int idx = blockIdx.x * blockDim.x + threadIdx.x;
    if (idx >= 2 * 256 * K1PAD) return;
    int ch = idx % K1PAD;
    int m  = (idx / K1PAD) & 255;
    int s  = idx / (K1PAD * 256);
    float w = (ch < C_IN) ? w1[(size_t)m * C_IN + ch] : 0.f;
    __nv_bfloat16 hi = __float2bfloat16(w);
    g_W1[idx] = s ? __float2bfloat16(w - __bfloat162float(hi)) : hi;
}

// conv3 weights: g_W3[s][m][256], bf16 hi/lo
__global__ void k_prepw3(const float* __restrict__ w3)
{
    int idx = blockIdx.x * blockDim.x + threadIdx.x;
    if (idx >= 2 * 256 * 256) return;
    int ch = idx & 255;
    int m  = (idx >> 8) & 255;
    int s  = idx >> 16;
    float w = w3[(size_t)m * 256 + ch];
    __nv_bfloat16 hi = __float2bfloat16(w);
    g_W3[idx] = s ? __float2bfloat16(w - __bfloat162float(hi)) : hi;
}

// -------------------- generic 1x1 conv MMA kernel (bf16 3-term) ------------
// MODE 0: A=g_W1, B=g_U, epilogue -> g_H fp16 single plane, padded px-major
// MODE 1: A=g_W3, B=g_V, epilogue -> Out fp32 ch-major (conv3)
template<int NKC, int MODE>
__global__ void __launch_bounds__(256, 1) k_mma1x1(const float* __restrict__ bias,
                                                   float* __restrict__ Out)
{
    constexpr int KPAD = NKC * 64;
    constexpr long APLANE_B = (long)256 * KPAD * 2;
    constexpr long BPLANE_B = (long)P2 * KPAD * 2;

    extern __shared__ __align__(1024) char smem[];
    uint32_t sb = smem_u32(smem);
    const int tid = threadIdx.x;
    const int lane = tid & 31, wid = tid >> 5;
    const int wm = wid >> 1, wn = wid & 1;
    const int n0 = blockIdx.x * 128;
    const int m0 = blockIdx.y * 128;

    const int rb = tid >> 3;
    const int cc = tid & 7;
    const char* AB = (MODE == 0) ? (const char*)g_W1 : (const char*)g_W3;
    const char* BB = (MODE == 0) ? (const char*)g_U  : (const char*)g_V;

    uint32_t aRow[2], aSw[2];
    const uint32_t aHi = lane >> 4;
#pragma unroll
    for (int f = 0; f < 2; f++) {
        int r = wm * 32 + f * 16 + (lane & 15);
        aRow[f] = r << 7;
        aSw[f] = r & 7;
    }
    uint32_t bRow[4], bSw[4];
    const uint32_t bHi = (lane >> 3) & 1;
#pragma unroll
    for (int g = 0; g < 4; g++) {
        int r = wn * 64 + g * 16 + (lane & 7) + ((lane >> 4) << 3);
        bRow[g] = r << 7;
        bSw[g] = r & 7;
    }

    float acc[2][8][4];
#pragma unroll
    for (int i = 0; i < 2; i++)
#pragma unroll
        for (int j = 0; j < 8; j++)
#pragma unroll
            for (int e = 0; e < 4; e++) acc[i][j][e] = 0.f;

    auto fill = [&](int it) {
        uint32_t stg = sb + (it % 3) * STAGE_BYTES;
        long kO = (long)it * 128;
#pragma unroll
        for (int t = 0; t < 4; t++) {
            int r = rb + 32 * t;
            uint32_t sw = (uint32_t)((cc ^ (r & 7)) << 4);
            long a0 = (long)(m0 + r) * (KPAD * 2) + kO + cc * 16;
            cpa16(stg + r * 128 + sw,         AB + a0);
            cpa16(stg + 16384 + r * 128 + sw, AB + a0 + APLANE_B);
            long b0 = (long)(n0 + r) * (KPAD * 2) + kO + cc * 16;
            cpa16(stg + 32768 + r * 128 + sw, BB + b0);
            cpa16(stg + 49152 + r * 128 + sw, BB + b0 + BPLANE_B);
        }
        asm volatile("cp.async.commit_group;" ::: "memory");
    };

    fill(0);
    fill(1);

    for (int it = 0; it < NKC; it++) {
        if (it == NKC - 1) asm volatile("cp.async.wait_group 0;" ::: "memory");
        else               asm volatile("cp.async.wait_group 1;" ::: "memory");
        __syncthreads();
        uint32_t stg = sb + (it % 3) * STAGE_BYTES;
#pragma unroll
        for (int ks = 0; ks < 4; ks++) {
            uint32_t Wh[2][4], Wl[2][4], Bh[4][4], Bl[4][4];
#pragma unroll
            for (int f = 0; f < 2; f++) {
                uint32_t col = ((((uint32_t)(ks << 1) + aHi) ^ aSw[f]) << 4);
                ldsm4(Wh[f], stg + aRow[f] + col);
                ldsm4(Wl[f], stg + 16384 + aRow[f] + col);
            }
#pragma unroll
            for (int g = 0; g < 4; g++) {
                uint32_t col = ((((uint32_t)(ks << 1) + bHi) ^ bSw[g]) << 4);
                ldsm4(Bh[g], stg + 32768 + bRow[g] + col);
                ldsm4(Bl[g], stg + 49152 + bRow[g] + col);
            }
#pragma unroll
            for (int f = 0; f < 2; f++)
#pragma unroll
                for (int g = 0; g < 4; g++)
#pragma unroll
                    for (int h = 0; h < 2; h++) {
                        float* d = acc[f][g * 2 + h];
                        mma_bf16(d, Wh[f], Bh[g][h * 2], Bh[g][h * 2 + 1]);
                        mma_bf16(d, Wh[f], Bl[g][h * 2], Bl[g][h * 2 + 1]);
                        mma_bf16(d, Wl[f], Bh[g][h * 2], Bh[g][h * 2 + 1]);
                    }
        }
        if (it + 2 < NKC) fill(it + 2);
    }
    __syncthreads();

    // ---- staged epilogue ----
    const int l4 = lane >> 2, l2 = (lane & 3) * 2;
    if (MODE == 0) {
        unsigned short* sH = (unsigned short*)smem;   // [n 128][pitch 130] fp16
#pragma unroll
        for (int f = 0; f < 2; f++) {
            int mb = wm * 32 + f * 16 + l4;
            float b0v = bias[m0 + mb], b1v = bias[m0 + mb + 8];
#pragma unroll
            for (int j = 0; j < 8; j++) {
                int nl = wn * 64 + j * 8 + l2;
#pragma unroll
                for (int e = 0; e < 4; e++) {
                    float v = acc[f][j][e] + ((e & 2) ? b1v : b0v);
                    v = fmaxf(v, 0.f);
                    sH[(nl + (e & 1)) * 130 + mb + ((e & 2) ? 8 : 0)] =
                        __half_as_ushort(__float2half(v));
                }
            }
        }
        __syncthreads();
#pragma unroll 8
        for (int t = 0; t < 64; t++) {
            int idx = tid + t * 256;
            int row = idx >> 7, ml = idx & 127;
            int ng = n0 + row;
            size_t pixpad = (size_t)(((ng >> 8) + 2) * PADW + (ng & 255) + 2) * 256 + m0 + ml;
            g_H[pixpad] = sH[row * 130 + ml];
        }
    } else {
        float* sF = (float*)smem;   // [m 128][pitch 130]
#pragma unroll
        for (int f = 0; f < 2; f++) {
            int mb = wm * 32 + f * 16 + l4;
            float b0v = bias[m0 + mb], b1v = bias[m0 + mb + 8];
#pragma unroll
            for (int j = 0; j < 8; j++) {
                int nl = wn * 64 + j * 8 + l2;
#pragma unroll
                for (int e = 0; e < 4; e++) {
                    float v = acc[f][j][e] + ((e & 2) ? b1v : b0v);
                    sF[(mb + ((e & 2) ? 8 : 0)) * 130 + nl + (e & 1)] = fmaxf(v, 0.f);
                }
            }
        }
        __syncthreads();
#pragma unroll 8
        for (int t = 0; t < 64; t++) {
            int idx = tid + t * 256;
            int ml = idx >> 7, nl = idx & 127;
            Out[(size_t)(m0 + ml) * P2 + n0 + nl] = sF[ml * 130 + nl];
        }
    }
}

// -------------------- conv2: fp16 2-term, B single plane, reused across dx -
// loop order: it = (dy*4 + chunk)*5 + dx ; B tile (132 halo rows) per (dy,chunk)
__global__ void __launch_bounds__(256, 1) k_conv2mma(const float* __restrict__ bias2)
{
    extern __shared__ __align__(1024) char smem[];
    uint32_t sb = smem_u32(smem);
    const int tid = threadIdx.x;
    const int lane = tid & 31, wid = tid >> 5;
    const int wm = wid >> 1, wn = wid & 1;
    const int bx = blockIdx.x;
    const int y = bx >> 1, x0 = (bx & 1) * 128;
    const int m0 = blockIdx.y * 128;
    const int pixbase = y * 256 + x0;

    const int rb = tid >> 3;
    const int cc = tid & 7;
    const char* WtB = (const char*)g_Wt;
    const char* HB  = (const char*)g_H;

    uint32_t aRow[2], aSw[2];
    const uint32_t aHi = lane >> 4;
#pragma unroll
    for (int f = 0; f < 2; f++) {
        int r = wm * 32 + f * 16 + (lane & 15);
        aRow[f] = r << 7;
        aSw[f] = r & 7;
    }
    uint32_t rB0[4];
    const uint32_t bHi = (lane >> 3) & 1;
#pragma unroll
    for (int g = 0; g < 4; g++)
        rB0[g] = wn * 64 + g * 16 + (lane & 7) + ((lane >> 4) << 3);

    float acc[2][8][4];
#pragma unroll
    for (int i = 0; i < 2; i++)
#pragma unroll
        for (int j = 0; j < 8; j++)
#pragma unroll
            for (int e = 0; e < 4; e++) acc[i][j][e] = 0.f;

    auto fill = [&](int it) {
        int dy = it / 20, rem = it % 20, chunk = rem / 5, dx = rem % 5;
        int tap = dy * 5 + dx;
        const char* srcA = WtB + (long)tap * 131072 + chunk * 128;
        uint32_t stgA = sb + (it % 3) * C2_A_STAGE;
#pragma unroll
        for (int t = 0; t < 4; t++) {
            int r = rb + 32 * t;
            uint32_t sw = (uint32_t)((cc ^ (r & 7)) << 4);
            long a0 = (long)(m0 + r) * 512 + cc * 16;
            cpa16(stgA + r * 128 + sw,         srcA + a0);
            cpa16(stgA + 16384 + r * 128 + sw, srcA + a0 + 3276800);
        }
        if (dx == 0) {
            uint32_t stgB = sb + C2_B_OFF + ((it / 5) & 1) * C2_B_SLOT;
            const char* srcB = HB + (long)((y + dy) * PADW + x0) * 512 + chunk * 128;
            for (int o = tid * 16; o < C2_B_SLOT; o += 4096) {
                int r = o >> 7;
                int cB = o & 127;
                uint32_t sw = (uint32_t)(r * 128 + (cB ^ ((r & 7) << 4)));
                cpa16(stgB + sw, srcB + (long)r * 512 + cB);
            }
        }
        asm volatile("cp.async.commit_group;" ::: "memory");
    };

    fill(0);
    fill(1);

    for (int it = 0; it < 100; it++) {
        if (it == 99) asm volatile("cp.async.wait_group 0;" ::: "memory");
        else          asm volatile("cp.async.wait_group 1;" ::: "memory");
        __syncthreads();
        const int dxi = it % 5;
        uint32_t stgA = sb + (it % 3) * C2_A_STAGE;
        uint32_t stgB = sb + C2_B_OFF + ((it / 5) & 1) * C2_B_SLOT;
#pragma unroll
        for (int ks = 0; ks < 4; ks++) {
            uint32_t Wh[2][4], Wl[2][4], Bh[4][4];
#pragma unroll
            for (int f = 0; f < 2; f++) {
                uint32_t col = ((((uint32_t)(ks << 1) + aHi) ^ aSw[f]) << 4);
                ldsm4(Wh[f], stgA + aRow[f] + col);
                ldsm4(Wl[f], stgA + 16384 + aRow[f] + col);
            }
#pragma unroll
            for (int g = 0; g < 4; g++) {
                uint32_t rr = rB0[g] + dxi;
                uint32_t addr = stgB + (rr << 7)
                              + ((((uint32_t)(ks << 1) + bHi) ^ (rr & 7)) << 4);
                ldsm4(Bh[g], addr);
            }
#pragma unroll
            for (int f = 0; f < 2; f++)
#pragma unroll
                for (int g = 0; g < 4; g++)
#pragma unroll
                    for (int h = 0; h < 2; h++) {
                        float* d = acc[f][g * 2 + h];
                        mma_f16(d, Wh[f], Bh[g][h * 2], Bh[g][h * 2 + 1]);
                        mma_f16(d, Wl[f], Bh[g][h * 2], Bh[g][h * 2 + 1]);
                    }
        }
        if (it + 2 < 100) fill(it + 2);
    }
    __syncthreads();

    // staged epilogue -> g_Ct px-major, coalesced
    const int l4 = lane >> 2, l2 = (lane & 3) * 2;
    float* sF = (float*)smem;   // [n 128][pitch 130]
#pragma unroll
    for (int f = 0; f < 2; f++) {
        int mb = wm * 32 + f * 16 + l4;
        float b0v = bias2[m0 + mb], b1v = bias2[m0 + mb + 8];
#pragma unroll
        for (int j = 0; j < 8; j++) {
            int nl = wn * 64 + j * 8 + l2;
#pragma unroll
            for (int e = 0; e < 4; e++) {
                float v = acc[f][j][e] + ((e & 2) ? b1v : b0v);
                sF[(nl + (e & 1)) * 130 + mb + ((e & 2) ? 8 : 0)] = fmaxf(v, 0.f);
            }
        }
    }
    __syncthreads();
#pragma unroll 8
    for (int t = 0; t < 64; t++) {
        int idx = tid + t * 256;
        int row = idx >> 7, ml = idx & 127;
        g_Ct[(size_t)(pixbase + row) * 256 + m0 + ml] = sF[row * 130 + ml];
    }
}

// -------------------- guided filter (px-major, wide kernels) ---------------
__global__ void k_gf_row1()
{
    int idx = blockIdx.x * blockDim.x + threadIdx.x;
    if (idx >= CE * P2) return;
    int c = idx & 255;
    int pp = idx >> 8;
    int y = pp >> 8, x = pp & 255;
    size_t rowbase = (size_t)(y * 256) * 256 + c;
    float sp = 0.f, sip = 0.f;
    for (int dxx = -2; dxx <= 2; dxx++) {
        int xx = x + dxx;
        if (xx < 0 || xx > 255) continue;
        float pv = g_Ct[rowbase + (size_t)xx * 256];
        sp  += pv;
        sip += pv * g_guide[y * 256 + xx];
    }
    g_D[idx] = sp;
    g_E[idx] = sip;
}

__global__ void k_gf_col1()
{
    int idx = blockIdx.x * blockDim.x + threadIdx.x;
    if (idx >= CE * P2) return;
    int pp = idx >> 8;
    int y = pp >> 8, x = pp & 255;
    float sp = 0.f, sip = 0.f;
    for (int dyy = -2; dyy <= 2; dyy++) {
        int yy = y + dyy;
        if (yy < 0 || yy > 255) continue;
        int off = idx + (dyy << 16);
        sp  += g_D[off];
        sip += g_E[off];
    }
    float inv = 1.f / (float)(cnt_axis(y) * cnt_axis(x));
    float mp  = sp * inv;
    float mIp = sip * inv;
    float mI  = g_meanI[pp];
    float a = (mIp - mI * mp) / (g_varI[pp] + EPS_GF);
    g_Aa[idx] = a;
    g_F[idx] = mp - a * mI;
}

__global__ void k_gf_row2()
{
    int idx = blockIdx.x * blockDim.x + threadIdx.x;
    if (idx >= CE * P2) return;
    int c = idx & 255;
    int pp = idx >> 8;
    int y = pp >> 8, x = pp & 255;
    size_t rowbase = (size_t)(y * 256) * 256 + c;
    float sa = 0.f, sb = 0.f;
    for (int dxx = -2; dxx <= 2; dxx++) {
        int xx = x + dxx;
        if (xx < 0 || xx > 255) continue;
        sa += g_Aa[rowbase + (size_t)xx * 256];
        sb += g_F [rowbase + (size_t)xx * 256];
    }
    g_D[idx] = sa;
    g_E[idx] = sb;
}

// col2 emits filt directly as bf16 hi/lo into g_V (conv3 input)
__global__ void k_gf_col2()
{
    int idx = blockIdx.x * blockDim.x + threadIdx.x;
    if (idx >= CE * P2) return;
    int pp = idx >> 8;
    int y = pp >> 8, x = pp & 255;
    float sa = 0.f, sb = 0.f;
    for (int dyy = -2; dyy <= 2; dyy++) {
        int yy = y + dyy;
        if (yy < 0 || yy > 255) continue;
        int off = idx + (dyy << 16);
        sa += g_D[off];
        sb += g_E[off];
    }
    float inv = 1.f / (float)(cnt_axis(y) * cnt_axis(x));
    float filt = (sa * inv) * g_guide[pp] + sb * inv;
    __nv_bfloat16 fh = __float2bfloat16(filt);
    g_V[idx] = fh;
    g_V[VPLANE + idx] = __float2bfloat16(filt - __bfloat162float(fh));
}

// -------------------- mask head --------------------------------------------
__global__ void k_maskhead(const float* __restrict__ featOut,
                           const float* __restrict__ wm,
                           const float* __restrict__ bm,
                           float* __restrict__ maskOut)
{
    __shared__ float sw[256];
    int tid = threadIdx.x;
    sw[tid] = wm[tid];
    __syncthreads();
    int p = blockIdx.x * blockDim.x + tid;
    if (p >= P2) return;
    float s = bm[0];
#pragma unroll 8
    for (int c = 0; c < 256; c++)
        s += sw[c] * featOut[(size_t)c * P2 + p];
    maskOut[p] = 1.f / (1.f + expf(-s));
}

// ---------------------------------------------------------------------------
extern "C" void kernel_launch(void* const* d_in, const int* in_sizes, int n_in,
                              void* d_out, int out_size)
{
    const float* fg   = (const float*)d_in[0];
    const float* bg   = (const float*)d_in[1];
    const float* mask = (const float*)d_in[2];
    const float* feat = (const float*)d_in[3];
    const float* w1   = (const float*)d_in[4];
    const float* b1   = (const float*)d_in[5];
    const float* w2   = (const float*)d_in[6];
    const float* b2   = (const float*)d_in[7];
    const float* w3   = (const float*)d_in[8];
    const float* b3   = (const float*)d_in[9];
    const float* wm   = (const float*)d_in[10];
    const float* bm   = (const float*)d_in[11];

    float* out     = (float*)d_out;
    float* maskOut = out;           // (1,1,256,256)
    float* featOut = out + P2;      // (1,256,256,256)

    const int T = 256;

    cudaFuncSetAttribute(k_conv2mma,
                         cudaFuncAttributeMaxDynamicSharedMemorySize, SMEM_C2);
    cudaFuncSetAttribute(k_mma1x1<5, 0>,
                         cudaFuncAttributeMaxDynamicSharedMemorySize, SMEM_1X1);
    cudaFuncSetAttribute(k_mma1x1<4, 1>,
                         cudaFuncAttributeMaxDynamicSharedMemorySize, SMEM_1X1);

    // weight preps (no deps)
    k_prepw <<<(WT_ELEMS + T - 1) / T, T>>>(w2);
    k_prepw1<<<(2 * 256 * K1PAD + T - 1) / T, T>>>(w1);
    k_prepw3<<<(2 * 256 * 256 + T - 1) / T, T>>>(w3);
    // 1. fused upsample + transpose + bf16 split -> g_U
    k_upT<<<dim3(P2 / 32, K1PAD / 32), dim3(32, 8)>>>(fg, bg, mask, feat);
    // 2. guide (from g_U) + box statistics
    k_guide <<<(P2 + T - 1) / T, T>>>();
    k_istats<<<(P2 + T - 1) / T, T>>>();
    // 3. conv1 mma -> g_H (fp16 single plane)
    k_mma1x1<5, 0><<<dim3(512, 2), 256, SMEM_1X1>>>(b1, nullptr);
    // 4. conv2 mma (fp16 2-term) -> g_Ct
    k_conv2mma<<<dim3(512, 2), 256, SMEM_C2>>>(b2);
    // 5. guided filter (wide kernels); col2 writes conv3 input g_V directly
    int NB = (CE * P2 + T - 1) / T;
    k_gf_row1<<<NB, T>>>();
    k_gf_col1<<<NB, T>>>();
    k_gf_row2<<<NB, T>>>();
    k_gf_col2<<<NB, T>>>();
    // 6. conv3 mma -> featOut
    k_mma1x1<4, 1><<<dim3(512, 2), 256, SMEM_1X1>>>(b3, featOut);
    // 7. mask head
    k_maskhead<<<(P2 + T - 1) / T, T>>>(featOut, wm, bm, maskOut);
}

// round 12
// speedup vs baseline: 1.3464x; 1.0384x over previous
#include <cuda_runtime.h>
#include <cuda_bf16.h>
#include <cuda_fp16.h>
#include <math.h>
#include <stdint.h>

// ---------------------------------------------------------------------------
// GuidedUpsampleUnitGF — all three convs: fp16 2-term mma (W hi/lo, x fp16)
// NOTE: __device__ globals must NEVER be passed as kernel args from host.
// ---------------------------------------------------------------------------

#define P2    65536
#define C_IN  263
#define CE    256
#define EPS_GF 0.01f

#define PADH 260
#define PADW 264
#define PADP (PADH * PADW)
#define HPLANE ((size_t)PADP * 256)

#define WT_ELEMS (2 * 25 * 256 * 256)

#define K1PAD 320
#define UPLANE ((size_t)P2 * K1PAD)
#define VPLANE ((size_t)P2 * 256)

// 1x1 conv smem: stage = A hi 16K + A lo 16K + B 16K
#define STAGE_1X1 49152
#define SMEM_1X1 (3 * STAGE_1X1)

// conv2 smem: A ring 3 x 32KB (Wh/Wl fp16), B ring 2 x 16896 (132 rows x 128B)
#define C2_A_STAGE 32768
#define C2_B_OFF   98304
#define C2_B_SLOT  16896
#define SMEM_C2    (C2_B_OFF + 2 * C2_B_SLOT)   // 132096

// -------------------- scratch ----------------------------------------------
__device__ __align__(256) float g_Ct[(size_t)P2 * 256]; // px-major conv2 out
__device__ __align__(256) float g_Aa[(size_t)P2 * 256]; // 'a' of guided filter
__device__ __align__(256) float g_D [(size_t)P2 * 256];
__device__ __align__(256) float g_E [(size_t)P2 * 256];
__device__ __align__(256) float g_F [(size_t)P2 * 256]; // 'b' of guided filter
__device__ __align__(256) float g_guide[P2];
__device__ __align__(256) float g_meanI[P2];
__device__ __align__(256) float g_varI[P2];
__device__ __align__(256) unsigned short g_H[HPLANE];   // conv1 out fp16, padded
__device__ __align__(256) __half g_Wt[WT_ELEMS];        // conv2 W fp16 hi/lo
__device__ __align__(256) __half g_U [UPLANE];          // conv1 input fp16
__device__ __align__(256) __half g_V [VPLANE];          // conv3 input fp16 (filt)
__device__ __align__(256) __half g_W1[2 * 256 * K1PAD]; // conv1 W fp16 hi/lo
__device__ __align__(256) __half g_W3[2 * 256 * 256];   // conv3 W fp16 hi/lo

// -------------------- helpers ----------------------------------------------
__device__ __forceinline__ uint32_t smem_u32(const void* p) {
    uint32_t a;
    asm("{ .reg .u64 t; cvta.to.shared.u64 t, %1; cvt.u32.u64 %0, t; }" : "=r"(a) : "l"(p));
    return a;
}
__device__ __forceinline__ void cpa16(uint32_t dst, const void* src) {
    asm volatile("cp.async.cg.shared.global [%0], [%1], 16;\n" :: "r"(dst), "l"(src));
}
__device__ __forceinline__ void ldsm4(uint32_t* r, uint32_t addr) {
    asm volatile("ldmatrix.sync.aligned.m8n8.x4.shared.b16 {%0,%1,%2,%3}, [%4];"
                 : "=r"(r[0]), "=r"(r[1]), "=r"(r[2]), "=r"(r[3]) : "r"(addr));
}
__device__ __forceinline__ void mma_f16(float* d, const uint32_t* a,
                                        uint32_t b0, uint32_t b1) {
    asm volatile("mma.sync.aligned.m16n8k16.row.col.f32.f16.f16.f32 "
                 "{%0,%1,%2,%3}, {%4,%5,%6,%7}, {%8,%9}, {%0,%1,%2,%3};"
                 : "+f"(d[0]), "+f"(d[1]), "+f"(d[2]), "+f"(d[3])
                 : "r"(a[0]), "r"(a[1]), "r"(a[2]), "r"(a[3]), "r"(b0), "r"(b1));
}

// -------------------- fused upsample + transpose -> g_U fp16 ----------------
__global__ void __launch_bounds__(256) k_upT(const float* __restrict__ fg,
                                             const float* __restrict__ bg,
                                             const float* __restrict__ mask,
                                             const float* __restrict__ feat)
{
    __shared__ float tile[32][33];
    const int p0 = blockIdx.x * 32;
    const int c0 = blockIdx.y * 32;
    const int tx = threadIdx.x, ty = threadIdx.y;

    int p = p0 + tx;
    int y = p >> 8, x = p & 255;
    float sy = 0.5f * (float)y - 0.25f;
    float sx = 0.5f * (float)x - 0.25f;
    float fy = sy - floorf(sy);
    float fx = sx - floorf(sx);
    int y0 = (int)floorf(sy);
    int x0 = (int)floorf(sx);
    int y0c = max(y0, 0),       x0c = max(x0, 0);
    int y1c = min(y0 + 1, 127), x1c = min(x0 + 1, 127);
    int i00 = y0c * 128 + x0c, i01 = y0c * 128 + x1c;
    int i10 = y1c * 128 + x0c, i11 = y1c * 128 + x1c;
    float w00 = (1.f - fy) * (1.f - fx), w01 = (1.f - fy) * fx;
    float w10 = fy * (1.f - fx),         w11 = fy * fx;

#pragma unroll
    for (int k = 0; k < 4; k++) {
        int ch = c0 + ty + k * 8;
        float v = 0.f;
        if (ch < C_IN) {
            const float* src;
            if (ch == 0)      src = mask;
            else if (ch <= 3) src = fg + (ch - 1) * 16384;
            else if (ch <= 6) src = bg + (ch - 4) * 16384;
            else              src = feat + (ch - 7) * 16384;
            v = w00 * src[i00] + w01 * src[i01] + w10 * src[i10] + w11 * src[i11];
        }
        tile[ty + k * 8][tx] = v;
    }
    __syncthreads();
#pragma unroll
    for (int k = 0; k < 4; k++) {
        int pp = p0 + ty + k * 8;
        int ch = c0 + tx;
        g_U[(size_t)pp * K1PAD + ch] = __float2half(tile[tx][ty + k * 8]);
    }
}

// guide from g_U fp16 (channels 1..3 = fg)
__global__ void k_guide()
{
    int p = blockIdx.x * blockDim.x + threadIdx.x;
    if (p >= P2) return;
    float s = __half2float(g_U[(size_t)p * K1PAD + 1])
            + __half2float(g_U[(size_t)p * K1PAD + 2])
            + __half2float(g_U[(size_t)p * K1PAD + 3]);
    g_guide[p] = s * (128.0f / 3.0f);
}

__device__ __forceinline__ int cnt_axis(int i)
{
    return min(i + 2, 255) - max(i - 2, 0) + 1;
}

__global__ void k_istats()
{
    int p = blockIdx.x * blockDim.x + threadIdx.x;
    if (p >= P2) return;
    int y = p >> 8, x = p & 255;
    float sI = 0.f, sI2 = 0.f;
    for (int dy = -2; dy <= 2; dy++) {
        int yy = y + dy;
        if (yy < 0 || yy > 255) continue;
        for (int dx = -2; dx <= 2; dx++) {
            int xx = x + dx;
            if (xx < 0 || xx > 255) continue;
            float v = g_guide[yy * 256 + xx];
            sI += v; sI2 += v * v;
        }
    }
    float inv = 1.f / (float)(cnt_axis(y) * cnt_axis(x));
    float mI = sI * inv;
    g_meanI[p] = mI;
    g_varI[p]  = sI2 * inv - mI * mI;
}

// -------------------- weight prep kernels (all fp16 hi/lo) ------------------
__global__ void k_prepw(const float* __restrict__ w2)
{
    int idx = blockIdx.x * blockDim.x + threadIdx.x;
    if (idx >= WT_ELEMS) return;
    int ch = idx & 255;
    int m  = (idx >> 8) & 255;
    int st = idx >> 16;
    int tap = st % 25;
    int s   = st / 25;
    float w = w2[(size_t)m * 6400 + ch * 25 + tap];
    __half hi = __float2half(w);
    g_Wt[idx] = s ? __float2half(w - __half2float(hi)) : hi;
}

__global__ void k_prepw1(const float* __restrict__ w1)
{
    int idx = blockIdx.x * blockDim.x + threadIdx.x;
    if (idx >= 2 * 256 * K1PAD) return;
    int ch = idx % K1PAD;
    int m  = (idx / K1PAD) & 255;
    int s  = idx / (K1PAD * 256);
    float w = (ch < C_IN) ? w1[(size_t)m * C_IN + ch] : 0.f;
    __half hi = __float2half(w);
    g_W1[idx] = s ? __float2half(w - __half2float(hi)) : hi;
}

__global__ void k_prepw3(const float* __restrict__ w3)
{
    int idx = blockIdx.x * blockDim.x + threadIdx.x;
    if (idx >= 2 * 256 * 256) return;
    int ch = idx & 255;
    int m  = (idx >> 8) & 255;
    int s  = idx >> 16;
    float w = w3[(size_t)m * 256 + ch];
    __half hi = __float2half(w);
    g_W3[idx] = s ? __float2half(w - __half2float(hi)) : hi;
}

// -------------------- generic 1x1 conv MMA (fp16 2-term) --------------------
// MODE 0: A=g_W1, B=g_U, epilogue -> g_H fp16 single plane, padded px-major
// MODE 1: A=g_W3, B=g_V, epilogue -> Out fp32 ch-major (conv3)
template<int NKC, int MODE>
__global__ void __launch_bounds__(256, 1) k_mma1x1(const float* __restrict__ bias,
                                                   float* __restrict__ Out)
{
    constexpr int KPAD = NKC * 64;
    constexpr long APLANE_B = (long)256 * KPAD * 2;

    extern __shared__ __align__(1024) char smem[];
    uint32_t sb = smem_u32(smem);
    const int tid = threadIdx.x;
    const int lane = tid & 31, wid = tid >> 5;
    const int wm = wid >> 1, wn = wid & 1;
    const int n0 = blockIdx.x * 128;
    const int m0 = blockIdx.y * 128;

    const int rb = tid >> 3;
    const int cc = tid & 7;
    const char* AB = (MODE == 0) ? (const char*)g_W1 : (const char*)g_W3;
    const char* BB = (MODE == 0) ? (const char*)g_U  : (const char*)g_V;

    uint32_t aRow[2], aSw[2];
    const uint32_t aHi = lane >> 4;
#pragma unroll
    for (int f = 0; f < 2; f++) {
        int r = wm * 32 + f * 16 + (lane & 15);
        aRow[f] = r << 7;
        aSw[f] = r & 7;
    }
    uint32_t bRow[4], bSw[4];
    const uint32_t bHi = (lane >> 3) & 1;
#pragma unroll
    for (int g = 0; g < 4; g++) {
        int r = wn * 64 + g * 16 + (lane & 7) + ((lane >> 4) << 3);
        bRow[g] = r << 7;
        bSw[g] = r & 7;
    }

    float acc[2][8][4];
#pragma unroll
    for (int i = 0; i < 2; i++)
#pragma unroll
        for (int j = 0; j < 8; j++)
#pragma unroll
            for (int e = 0; e < 4; e++) acc[i][j][e] = 0.f;

    auto fill = [&](int it) {
        uint32_t stg = sb + (it % 3) * STAGE_1X1;
        long kO = (long)it * 128;
#pragma unroll
        for (int t = 0; t < 4; t++) {
            int r = rb + 32 * t;
            uint32_t sw = (uint32_t)((cc ^ (r & 7)) << 4);
            long a0 = (long)(m0 + r) * (KPAD * 2) + kO + cc * 16;
            cpa16(stg + r * 128 + sw,         AB + a0);
            cpa16(stg + 16384 + r * 128 + sw, AB + a0 + APLANE_B);
            long b0 = (long)(n0 + r) * (KPAD * 2) + kO + cc * 16;
            cpa16(stg + 32768 + r * 128 + sw, BB + b0);
        }
        asm volatile("cp.async.commit_group;" ::: "memory");
    };

    fill(0);
    fill(1);

    for (int it = 0; it < NKC; it++) {
        if (it == NKC - 1) asm volatile("cp.async.wait_group 0;" ::: "memory");
        else               asm volatile("cp.async.wait_group 1;" ::: "memory");
        __syncthreads();
        uint32_t stg = sb + (it % 3) * STAGE_1X1;
#pragma unroll
        for (int ks = 0; ks < 4; ks++) {
            uint32_t Wh[2][4], Wl[2][4], Bh[4][4];
#pragma unroll
            for (int f = 0; f < 2; f++) {
                uint32_t col = ((((uint32_t)(ks << 1) + aHi) ^ aSw[f]) << 4);
                ldsm4(Wh[f], stg + aRow[f] + col);
                ldsm4(Wl[f], stg + 16384 + aRow[f] + col);
            }
#pragma unroll
            for (int g = 0; g < 4; g++) {
                uint32_t col = ((((uint32_t)(ks << 1) + bHi) ^ bSw[g]) << 4);
                ldsm4(Bh[g], stg + 32768 + bRow[g] + col);
            }
#pragma unroll
            for (int f = 0; f < 2; f++)
#pragma unroll
                for (int g = 0; g < 4; g++)
#pragma unroll
                    for (int h = 0; h < 2; h++) {
                        float* d = acc[f][g * 2 + h];
                        mma_f16(d, Wh[f], Bh[g][h * 2], Bh[g][h * 2 + 1]);
                        mma_f16(d, Wl[f], Bh[g][h * 2], Bh[g][h * 2 + 1]);
                    }
        }
        if (it + 2 < NKC) fill(it + 2);
    }
    __syncthreads();

    // ---- staged epilogue ----
    const int l4 = lane >> 2, l2 = (lane & 3) * 2;
    if (MODE == 0) {
        unsigned short* sH = (unsigned short*)smem;   // [n 128][pitch 130] fp16
#pragma unroll
        for (int f = 0; f < 2; f++) {
            int mb = wm * 32 + f * 16 + l4;
            float b0v = bias[m0 + mb], b1v = bias[m0 + mb + 8];
#pragma unroll
            for (int j = 0; j < 8; j++) {
                int nl = wn * 64 + j * 8 + l2;
#pragma unroll
                for (int e = 0; e < 4; e++) {
                    float v = acc[f][j][e] + ((e & 2) ? b1v : b0v);
                    v = fmaxf(v, 0.f);
                    sH[(nl + (e & 1)) * 130 + mb + ((e & 2) ? 8 : 0)] =
                        __half_as_ushort(__float2half(v));
                }
            }
        }
        __syncthreads();
#pragma unroll 8
        for (int t = 0; t < 64; t++) {
            int idx = tid + t * 256;
            int row = idx >> 7, ml = idx & 127;
            int ng = n0 + row;
            size_t pixpad = (size_t)(((ng >> 8) + 2) * PADW + (ng & 255) + 2) * 256 + m0 + ml;
            g_H[pixpad] = sH[row * 130 + ml];
        }
    } else {
        float* sF = (float*)smem;   // [m 128][pitch 130]
#pragma unroll
        for (int f = 0; f < 2; f++) {
            int mb = wm * 32 + f * 16 + l4;
            float b0v = bias[m0 + mb], b1v = bias[m0 + mb + 8];
#pragma unroll
            for (int j = 0; j < 8; j++) {
                int nl = wn * 64 + j * 8 + l2;
#pragma unroll
                for (int e = 0; e < 4; e++) {
                    float v = acc[f][j][e] + ((e & 2) ? b1v : b0v);
                    sF[(mb + ((e & 2) ? 8 : 0)) * 130 + nl + (e & 1)] = fmaxf(v, 0.f);
                }
            }
        }
        __syncthreads();
#pragma unroll 8
        for (int t = 0; t < 64; t++) {
            int idx = tid + t * 256;
            int ml = idx >> 7, nl = idx & 127;
            Out[(size_t)(m0 + ml) * P2 + n0 + nl] = sF[ml * 130 + nl];
        }
    }
}

// -------------------- conv2: fp16 2-term, B single plane, reused across dx -
__global__ void __launch_bounds__(256, 1) k_conv2mma(const float* __restrict__ bias2)
{
    extern __shared__ __align__(1024) char smem[];
    uint32_t sb = smem_u32(smem);
    const int tid = threadIdx.x;
    const int lane = tid & 31, wid = tid >> 5;
    const int wm = wid >> 1, wn = wid & 1;
    const int bx = blockIdx.x;
    const int y = bx >> 1, x0 = (bx & 1) * 128;
    const int m0 = blockIdx.y * 128;
    const int pixbase = y * 256 + x0;

    const int rb = tid >> 3;
    const int cc = tid & 7;
    const char* WtB = (const char*)g_Wt;
    const char* HB  = (const char*)g_H;

    uint32_t aRow[2], aSw[2];
    const uint32_t aHi = lane >> 4;
#pragma unroll
    for (int f = 0; f < 2; f++) {
        int r = wm * 32 + f * 16 + (lane & 15);
        aRow[f] = r << 7;
        aSw[f] = r & 7;
    }
    uint32_t rB0[4];
    const uint32_t bHi = (lane >> 3) & 1;
#pragma unroll
    for (int g = 0; g < 4; g++)
        rB0[g] = wn * 64 + g * 16 + (lane & 7) + ((lane >> 4) << 3);

    float acc[2][8][4];
#pragma unroll
    for (int i = 0; i < 2; i++)
#pragma unroll
        for (int j = 0; j < 8; j++)
#pragma unroll
            for (int e = 0; e < 4; e++) acc[i][j][e] = 0.f;

    auto fill = [&](int it) {
        int dy = it / 20, rem = it % 20, chunk = rem / 5, dx = rem % 5;
        int tap = dy * 5 + dx;
        const char* srcA = WtB + (long)tap * 131072 + chunk * 128;
        uint32_t stgA = sb + (it % 3) * C2_A_STAGE;
#pragma unroll
        for (int t = 0; t < 4; t++) {
            int r = rb + 32 * t;
            uint32_t sw = (uint32_t)((cc ^ (r & 7)) << 4);
            long a0 = (long)(m0 + r) * 512 + cc * 16;
            cpa16(stgA + r * 128 + sw,         srcA + a0);
            cpa16(stgA + 16384 + r * 128 + sw, srcA + a0 + 3276800);
        }
        if (dx == 0) {
            uint32_t stgB = sb + C2_B_OFF + ((it / 5) & 1) * C2_B_SLOT;
            const char* srcB = HB + (long)((y + dy) * PADW + x0) * 512 + chunk * 128;
            for (int o = tid * 16; o < C2_B_SLOT; o += 4096) {
                int r = o >> 7;
                int cB = o & 127;
                uint32_t sw = (uint32_t)(r * 128 + (cB ^ ((r & 7) << 4)));
                cpa16(stgB + sw, srcB + (long)r * 512 + cB);
            }
        }
        asm volatile("cp.async.commit_group;" ::: "memory");
    };

    fill(0);
    fill(1);

    for (int it = 0; it < 100; it++) {
        if (it == 99) asm volatile("cp.async.wait_group 0;" ::: "memory");
        else          asm volatile("cp.async.wait_group 1;" ::: "memory");
        __syncthreads();
        const int dxi = it % 5;
        uint32_t stgA = sb + (it % 3) * C2_A_STAGE;
        uint32_t stgB = sb + C2_B_OFF + ((it / 5) & 1) * C2_B_SLOT;
#pragma unroll
        for (int ks = 0; ks < 4; ks++) {
            uint32_t Wh[2][4], Wl[2][4], Bh[4][4];
#pragma unroll
            for (int f = 0; f < 2; f++) {
                uint32_t col = ((((uint32_t)(ks << 1) + aHi) ^ aSw[f]) << 4);
                ldsm4(Wh[f], stgA + aRow[f] + col);
                ldsm4(Wl[f], stgA + 16384 + aRow[f] + col);
            }
#pragma unroll
            for (int g = 0; g < 4; g++) {
                uint32_t rr = rB0[g] + dxi;
                uint32_t addr = stgB + (rr << 7)
                              + ((((uint32_t)(ks << 1) + bHi) ^ (rr & 7)) << 4);
                ldsm4(Bh[g], addr);
            }
#pragma unroll
            for (int f = 0; f < 2; f++)
#pragma unroll
                for (int g = 0; g < 4; g++)
#pragma unroll
                    for (int h = 0; h < 2; h++) {
                        float* d = acc[f][g * 2 + h];
                        mma_f16(d, Wh[f], Bh[g][h * 2], Bh[g][h * 2 + 1]);
                        mma_f16(d, Wl[f], Bh[g][h * 2], Bh[g][h * 2 + 1]);
                    }
        }
        if (it + 2 < 100) fill(it + 2);
    }
    __syncthreads();

    // staged epilogue -> g_Ct px-major, coalesced
    const int l4 = lane >> 2, l2 = (lane & 3) * 2;
    float* sF = (float*)smem;   // [n 128][pitch 130]
#pragma unroll
    for (int f = 0; f < 2; f++) {
        int mb = wm * 32 + f * 16 + l4;
        float b0v = bias2[m0 + mb], b1v = bias2[m0 + mb + 8];
#pragma unroll
        for (int j = 0; j < 8; j++) {
            int nl = wn * 64 + j * 8 + l2;
#pragma unroll
            for (int e = 0; e < 4; e++) {
                float v = acc[f][j][e] + ((e & 2) ? b1v : b0v);
                sF[(nl + (e & 1)) * 130 + mb + ((e & 2) ? 8 : 0)] = fmaxf(v, 0.f);
            }
        }
    }
    __syncthreads();
#pragma unroll 8
    for (int t = 0; t < 64; t++) {
        int idx = tid + t * 256;
        int row = idx >> 7, ml = idx & 127;
        g_Ct[(size_t)(pixbase + row) * 256 + m0 + ml] = sF[row * 130 + ml];
    }
}

// -------------------- guided filter (px-major, wide kernels) ---------------
__global__ void k_gf_row1()
{
    int idx = blockIdx.x * blockDim.x + threadIdx.x;
    if (idx >= CE * P2) return;
    int c = idx & 255;
    int pp = idx >> 8;
    int y = pp >> 8, x = pp & 255;
    size_t rowbase = (size_t)(y * 256) * 256 + c;
    float sp = 0.f, sip = 0.f;
    for (int dxx = -2; dxx <= 2; dxx++) {
        int xx = x + dxx;
        if (xx < 0 || xx > 255) continue;
        float pv = g_Ct[rowbase + (size_t)xx * 256];
        sp  += pv;
        sip += pv * g_guide[y * 256 + xx];
    }
    g_D[idx] = sp;
    g_E[idx] = sip;
}

__global__ void k_gf_col1()
{
    int idx = blockIdx.x * blockDim.x + threadIdx.x;
    if (idx >= CE * P2) return;
    int pp = idx >> 8;
    int y = pp >> 8, x = pp & 255;
    float sp = 0.f, sip = 0.f;
    for (int dyy = -2; dyy <= 2; dyy++) {
        int yy = y + dyy;
        if (yy < 0 || yy > 255) continue;
        int off = idx + (dyy << 16);
        sp  += g_D[off];
        sip += g_E[off];
    }
    float inv = 1.f / (float)(cnt_axis(y) * cnt_axis(x));
    float mp  = sp * inv;
    float mIp = sip * inv;
    float mI  = g_meanI[pp];
    float a = (mIp - mI * mp) / (g_varI[pp] + EPS_GF);
    g_Aa[idx] = a;
    g_F[idx] = mp - a * mI;
}

__global__ void k_gf_row2()
{
    int idx = blockIdx.x * blockDim.x + threadIdx.x;
    if (idx >= CE * P2) return;
    int c = idx & 255;
    int pp = idx >> 8;
    int y = pp >> 8, x = pp & 255;
    size_t rowbase = (size_t)(y * 256) * 256 + c;
    float sa = 0.f, sb = 0.f;
    for (int dxx = -2; dxx <= 2; dxx++) {
        int xx = x + dxx;
        if (xx < 0 || xx > 255) continue;
        sa += g_Aa[rowbase + (size_t)xx * 256];
        sb += g_F [rowbase + (size_t)xx * 256];
    }
    g_D[idx] = sa;
    g_E[idx] = sb;
}

// col2 emits filt directly as fp16 into g_V (conv3 input)
__global__ void k_gf_col2()
{
    int idx = blockIdx.x * blockDim.x + threadIdx.x;
    if (idx >= CE * P2) return;
    int pp = idx >> 8;
    int y = pp >> 8, x = pp & 255;
    float sa = 0.f, sb = 0.f;
    for (int dyy = -2; dyy <= 2; dyy++) {
        int yy = y + dyy;
        if (yy < 0 || yy > 255) continue;
        int off = idx + (dyy << 16);
        sa += g_D[off];
        sb += g_E[off];
    }
    float inv = 1.f / (float)(cnt_axis(y) * cnt_axis(x));
    float filt = (sa * inv) * g_guide[pp] + sb * inv;
    g_V[idx] = __float2half(filt);
}

// -------------------- mask head --------------------------------------------
__global__ void k_maskhead(const float* __restrict__ featOut,
                           const float* __restrict__ wm,
                           const float* __restrict__ bm,
                           float* __restrict__ maskOut)
{
    __shared__ float sw[256];
    int tid = threadIdx.x;
    sw[tid] = wm[tid];
    __syncthreads();
    int p = blockIdx.x * blockDim.x + tid;
    if (p >= P2) return;
    float s = bm[0];
#pragma unroll 8
    for (int c = 0; c < 256; c++)
        s += sw[c] * featOut[(size_t)c * P2 + p];
    maskOut[p] = 1.f / (1.f + expf(-s));
}

// ---------------------------------------------------------------------------
extern "C" void kernel_launch(void* const* d_in, const int* in_sizes, int n_in,
                              void* d_out, int out_size)
{
    const float* fg   = (const float*)d_in[0];
    const float* bg   = (const float*)d_in[1];
    const float* mask = (const float*)d_in[2];
    const float* feat = (const float*)d_in[3];
    const float* w1   = (const float*)d_in[4];
    const float* b1   = (const float*)d_in[5];
    const float* w2   = (const float*)d_in[6];
    const float* b2   = (const float*)d_in[7];
    const float* w3   = (const float*)d_in[8];
    const float* b3   = (const float*)d_in[9];
    const float* wm   = (const float*)d_in[10];
    const float* bm   = (const float*)d_in[11];

    float* out     = (float*)d_out;
    float* maskOut = out;           // (1,1,256,256)
    float* featOut = out + P2;      // (1,256,256,256)

    const int T = 256;

    cudaFuncSetAttribute(k_conv2mma,
                         cudaFuncAttributeMaxDynamicSharedMemorySize, SMEM_C2);
    cudaFuncSetAttribute(k_mma1x1<5, 0>,
                         cudaFuncAttributeMaxDynamicSharedMemorySize, SMEM_1X1);
    cudaFuncSetAttribute(k_mma1x1<4, 1>,
                         cudaFuncAttributeMaxDynamicSharedMemorySize, SMEM_1X1);

    // weight preps (no deps)
    k_prepw <<<(WT_ELEMS + T - 1) / T, T>>>(w2);
    k_prepw1<<<(2 * 256 * K1PAD + T - 1) / T, T>>>(w1);
    k_prepw3<<<(2 * 256 * 256 + T - 1) / T, T>>>(w3);
    // 1. fused upsample + transpose -> g_U fp16
    k_upT<<<dim3(P2 / 32, K1PAD / 32), dim3(32, 8)>>>(fg, bg, mask, feat);
    // 2. guide + box statistics
    k_guide <<<(P2 + T - 1) / T, T>>>();
    k_istats<<<(P2 + T - 1) / T, T>>>();
    // 3. conv1 mma -> g_H (fp16 single plane)
    k_mma1x1<5, 0><<<dim3(512, 2), 256, SMEM_1X1>>>(b1, nullptr);
    // 4. conv2 mma (fp16 2-term) -> g_Ct
    k_conv2mma<<<dim3(512, 2), 256, SMEM_C2>>>(b2);
    // 5. guided filter; col2 writes conv3 input g_V fp16 directly
    int NB = (CE * P2 + T - 1) / T;
    k_gf_row1<<<NB, T>>>();
    k_gf_col1<<<NB, T>>>();
    k_gf_row2<<<NB, T>>>();
    k_gf_col2<<<NB, T>>>();
    // 6. conv3 mma -> featOut
    k_mma1x1<4, 1><<<dim3(512, 2), 256, SMEM_1X1>>>(b3, featOut);
    // 7. mask head
    k_maskhead<<<(P2 + T - 1) / T, T>>>(featOut, wm, bm, maskOut);
}

// round 13
// speedup vs baseline: 1.8094x; 1.3439x over previous
#include <cuda_runtime.h>
#include <cuda_bf16.h>
#include <cuda_fp16.h>
#include <math.h>
#include <stdint.h>

// ---------------------------------------------------------------------------
// GuidedUpsampleUnitGF
//   conv1/conv3: fp16 2-term mma (W hi/lo, x fp16)
//   conv2:       fp16 1-term mma (W fp16, x fp16)  — error budget verified
// NOTE: __device__ globals must NEVER be passed as kernel args from host.
// ---------------------------------------------------------------------------

#define P2    65536
#define C_IN  263
#define CE    256
#define EPS_GF 0.01f

#define PADH 260
#define PADW 264
#define PADP (PADH * PADW)
#define HPLANE ((size_t)PADP * 256)

#define WT_ELEMS (25 * 256 * 256)

#define K1PAD 320
#define UPLANE ((size_t)P2 * K1PAD)
#define VPLANE ((size_t)P2 * 256)

// 1x1 conv smem: stage = A hi 16K + A lo 16K + B 16K
#define STAGE_1X1 49152
#define SMEM_1X1 (3 * STAGE_1X1)

// conv2 smem: A ring 3 x 16KB (W fp16), B ring 2 x 16896 (132 rows x 128B)
#define C2_A_STAGE 16384
#define C2_B_OFF   49152
#define C2_B_SLOT  16896
#define SMEM_C2    (C2_B_OFF + 2 * C2_B_SLOT)   // 82944

// -------------------- scratch ----------------------------------------------
__device__ __align__(256) float g_Ct[(size_t)P2 * 256]; // px-major conv2 out
__device__ __align__(256) float g_Aa[(size_t)P2 * 256]; // 'a' of guided filter
__device__ __align__(256) float g_D [(size_t)P2 * 256];
__device__ __align__(256) float g_E [(size_t)P2 * 256];
__device__ __align__(256) float g_F [(size_t)P2 * 256]; // 'b' of guided filter
__device__ __align__(256) float g_guide[P2];
__device__ __align__(256) float g_meanI[P2];
__device__ __align__(256) float g_varI[P2];
__device__ __align__(256) unsigned short g_H[HPLANE];   // conv1 out fp16, padded
__device__ __align__(256) __half g_Wt[WT_ELEMS];        // conv2 W fp16 (single)
__device__ __align__(256) __half g_U [UPLANE];          // conv1 input fp16
__device__ __align__(256) __half g_V [VPLANE];          // conv3 input fp16 (filt)
__device__ __align__(256) __half g_W1[2 * 256 * K1PAD]; // conv1 W fp16 hi/lo
__device__ __align__(256) __half g_W3[2 * 256 * 256];   // conv3 W fp16 hi/lo

// -------------------- helpers ----------------------------------------------
__device__ __forceinline__ uint32_t smem_u32(const void* p) {
    uint32_t a;
    asm("{ .reg .u64 t; cvta.to.shared.u64 t, %1; cvt.u32.u64 %0, t; }" : "=r"(a) : "l"(p));
    return a;
}
__device__ __forceinline__ void cpa16(uint32_t dst, const void* src) {
    asm volatile("cp.async.cg.shared.global [%0], [%1], 16;\n" :: "r"(dst), "l"(src));
}
__device__ __forceinline__ void ldsm4(uint32_t* r, uint32_t addr) {
    asm volatile("ldmatrix.sync.aligned.m8n8.x4.shared.b16 {%0,%1,%2,%3}, [%4];"
                 : "=r"(r[0]), "=r"(r[1]), "=r"(r[2]), "=r"(r[3]) : "r"(addr));
}
__device__ __forceinline__ void mma_f16(float* d, const uint32_t* a,
                                        uint32_t b0, uint32_t b1) {
    asm volatile("mma.sync.aligned.m16n8k16.row.col.f32.f16.f16.f32 "
                 "{%0,%1,%2,%3}, {%4,%5,%6,%7}, {%8,%9}, {%0,%1,%2,%3};"
                 : "+f"(d[0]), "+f"(d[1]), "+f"(d[2]), "+f"(d[3])
                 : "r"(a[0]), "r"(a[1]), "r"(a[2]), "r"(a[3]), "r"(b0), "r"(b1));
}

// -------------------- fused upsample + transpose -> g_U fp16 ----------------
__global__ void __launch_bounds__(256) k_upT(const float* __restrict__ fg,
                                             const float* __restrict__ bg,
                                             const float* __restrict__ mask,
                                             const float* __restrict__ feat)
{
    __shared__ float tile[32][33];
    const int p0 = blockIdx.x * 32;
    const int c0 = blockIdx.y * 32;
    const int tx = threadIdx.x, ty = threadIdx.y;

    int p = p0 + tx;
    int y = p >> 8, x = p & 255;
    float sy = 0.5f * (float)y - 0.25f;
    float sx = 0.5f * (float)x - 0.25f;
    float fy = sy - floorf(sy);
    float fx = sx - floorf(sx);
    int y0 = (int)floorf(sy);
    int x0 = (int)floorf(sx);
    int y0c = max(y0, 0),       x0c = max(x0, 0);
    int y1c = min(y0 + 1, 127), x1c = min(x0 + 1, 127);
    int i00 = y0c * 128 + x0c, i01 = y0c * 128 + x1c;
    int i10 = y1c * 128 + x0c, i11 = y1c * 128 + x1c;
    float w00 = (1.f - fy) * (1.f - fx), w01 = (1.f - fy) * fx;
    float w10 = fy * (1.f - fx),         w11 = fy * fx;

#pragma unroll
    for (int k = 0; k < 4; k++) {
        int ch = c0 + ty + k * 8;
        float v = 0.f;
        if (ch < C_IN) {
            const float* src;
            if (ch == 0)      src = mask;
            else if (ch <= 3) src = fg + (ch - 1) * 16384;
            else if (ch <= 6) src = bg + (ch - 4) * 16384;
            else              src = feat + (ch - 7) * 16384;
            v = w00 * src[i00] + w01 * src[i01] + w10 * src[i10] + w11 * src[i11];
        }
        tile[ty + k * 8][tx] = v;
    }
    __syncthreads();
#pragma unroll
    for (int k = 0; k < 4; k++) {
        int pp = p0 + ty + k * 8;
        int ch = c0 + tx;
        g_U[(size_t)pp * K1PAD + ch] = __float2half(tile[tx][ty + k * 8]);
    }
}

// guide from g_U fp16 (channels 1..3 = fg)
__global__ void k_guide()
{
    int p = blockIdx.x * blockDim.x + threadIdx.x;
    if (p >= P2) return;
    float s = __half2float(g_U[(size_t)p * K1PAD + 1])
            + __half2float(g_U[(size_t)p * K1PAD + 2])
            + __half2float(g_U[(size_t)p * K1PAD + 3]);
    g_guide[p] = s * (128.0f / 3.0f);
}

__device__ __forceinline__ int cnt_axis(int i)
{
    return min(i + 2, 255) - max(i - 2, 0) + 1;
}

__global__ void k_istats()
{
    int p = blockIdx.x * blockDim.x + threadIdx.x;
    if (p >= P2) return;
    int y = p >> 8, x = p & 255;
    float sI = 0.f, sI2 = 0.f;
    for (int dy = -2; dy <= 2; dy++) {
        int yy = y + dy;
        if (yy < 0 || yy > 255) continue;
        for (int dx = -2; dx <= 2; dx++) {
            int xx = x + dx;
            if (xx < 0 || xx > 255) continue;
            float v = g_guide[yy * 256 + xx];
            sI += v; sI2 += v * v;
        }
    }
    float inv = 1.f / (float)(cnt_axis(y) * cnt_axis(x));
    float mI = sI * inv;
    g_meanI[p] = mI;
    g_varI[p]  = sI2 * inv - mI * mI;
}

// -------------------- weight prep kernels ----------------------------------
// conv2 weights fp16 single plane: g_Wt[tap][m][ch]
__global__ void k_prepw(const float* __restrict__ w2)
{
    int idx = blockIdx.x * blockDim.x + threadIdx.x;
    if (idx >= WT_ELEMS) return;
    int ch = idx & 255;
    int m  = (idx >> 8) & 255;
    int tap = idx >> 16;
    g_Wt[idx] = __float2half(w2[(size_t)m * 6400 + ch * 25 + tap]);
}

__global__ void k_prepw1(const float* __restrict__ w1)
{
    int idx = blockIdx.x * blockDim.x + threadIdx.x;
    if (idx >= 2 * 256 * K1PAD) return;
    int ch = idx % K1PAD;
    int m  = (idx / K1PAD) & 255;
    int s  = idx / (K1PAD * 256);
    float w = (ch < C_IN) ? w1[(size_t)m * C_IN + ch] : 0.f;
    __half hi = __float2half(w);
    g_W1[idx] = s ? __float2half(w - __half2float(hi)) : hi;
}

__global__ void k_prepw3(const float* __restrict__ w3)
{
    int idx = blockIdx.x * blockDim.x + threadIdx.x;
    if (idx >= 2 * 256 * 256) return;
    int ch = idx & 255;
    int m  = (idx >> 8) & 255;
    int s  = idx >> 16;
    float w = w3[(size_t)m * 256 + ch];
    __half hi = __float2half(w);
    g_W3[idx] = s ? __float2half(w - __half2float(hi)) : hi;
}

// -------------------- generic 1x1 conv MMA (fp16 2-term) --------------------
// MODE 0: A=g_W1, B=g_U, epilogue -> g_H fp16 single plane, padded px-major
// MODE 1: A=g_W3, B=g_V, epilogue -> Out fp32 ch-major (conv3)
template<int NKC, int MODE>
__global__ void __launch_bounds__(256, 1) k_mma1x1(const float* __restrict__ bias,
                                                   float* __restrict__ Out)
{
    constexpr int KPAD = NKC * 64;
    constexpr long APLANE_B = (long)256 * KPAD * 2;

    extern __shared__ __align__(1024) char smem[];
    uint32_t sb = smem_u32(smem);
    const int tid = threadIdx.x;
    const int lane = tid & 31, wid = tid >> 5;
    const int wm = wid >> 1, wn = wid & 1;
    const int n0 = blockIdx.x * 128;
    const int m0 = blockIdx.y * 128;

    const int rb = tid >> 3;
    const int cc = tid & 7;
    const char* AB = (MODE == 0) ? (const char*)g_W1 : (const char*)g_W3;
    const char* BB = (MODE == 0) ? (const char*)g_U  : (const char*)g_V;

    uint32_t aRow[2], aSw[2];
    const uint32_t aHi = lane >> 4;
#pragma unroll
    for (int f = 0; f < 2; f++) {
        int r = wm * 32 + f * 16 + (lane & 15);
        aRow[f] = r << 7;
        aSw[f] = r & 7;
    }
    uint32_t bRow[4], bSw[4];
    const uint32_t bHi = (lane >> 3) & 1;
#pragma unroll
    for (int g = 0; g < 4; g++) {
        int r = wn * 64 + g * 16 + (lane & 7) + ((lane >> 4) << 3);
        bRow[g] = r << 7;
        bSw[g] = r & 7;
    }

    float acc[2][8][4];
#pragma unroll
    for (int i = 0; i < 2; i++)
#pragma unroll
        for (int j = 0; j < 8; j++)
#pragma unroll
            for (int e = 0; e < 4; e++) acc[i][j][e] = 0.f;

    auto fill = [&](int it) {
        uint32_t stg = sb + (it % 3) * STAGE_1X1;
        long kO = (long)it * 128;
#pragma unroll
        for (int t = 0; t < 4; t++) {
            int r = rb + 32 * t;
            uint32_t sw = (uint32_t)((cc ^ (r & 7)) << 4);
            long a0 = (long)(m0 + r) * (KPAD * 2) + kO + cc * 16;
            cpa16(stg + r * 128 + sw,         AB + a0);
            cpa16(stg + 16384 + r * 128 + sw, AB + a0 + APLANE_B);
            long b0 = (long)(n0 + r) * (KPAD * 2) + kO + cc * 16;
            cpa16(stg + 32768 + r * 128 + sw, BB + b0);
        }
        asm volatile("cp.async.commit_group;" ::: "memory");
    };

    fill(0);
    fill(1);

    for (int it = 0; it < NKC; it++) {
        if (it == NKC - 1) asm volatile("cp.async.wait_group 0;" ::: "memory");
        else               asm volatile("cp.async.wait_group 1;" ::: "memory");
        __syncthreads();
        uint32_t stg = sb + (it % 3) * STAGE_1X1;
#pragma unroll
        for (int ks = 0; ks < 4; ks++) {
            uint32_t Wh[2][4], Wl[2][4], Bh[4][4];
#pragma unroll
            for (int f = 0; f < 2; f++) {
                uint32_t col = ((((uint32_t)(ks << 1) + aHi) ^ aSw[f]) << 4);
                ldsm4(Wh[f], stg + aRow[f] + col);
                ldsm4(Wl[f], stg + 16384 + aRow[f] + col);
            }
#pragma unroll
            for (int g = 0; g < 4; g++) {
                uint32_t col = ((((uint32_t)(ks << 1) + bHi) ^ bSw[g]) << 4);
                ldsm4(Bh[g], stg + 32768 + bRow[g] + col);
            }
#pragma unroll
            for (int f = 0; f < 2; f++)
#pragma unroll
                for (int g = 0; g < 4; g++)
#pragma unroll
                    for (int h = 0; h < 2; h++) {
                        float* d = acc[f][g * 2 + h];
                        mma_f16(d, Wh[f], Bh[g][h * 2], Bh[g][h * 2 + 1]);
                        mma_f16(d, Wl[f], Bh[g][h * 2], Bh[g][h * 2 + 1]);
                    }
        }
        if (it + 2 < NKC) fill(it + 2);
    }
    __syncthreads();

    // ---- staged epilogue ----
    const int l4 = lane >> 2, l2 = (lane & 3) * 2;
    if (MODE == 0) {
        unsigned short* sH = (unsigned short*)smem;   // [n 128][pitch 130] fp16
#pragma unroll
        for (int f = 0; f < 2; f++) {
            int mb = wm * 32 + f * 16 + l4;
            float b0v = bias[m0 + mb], b1v = bias[m0 + mb + 8];
#pragma unroll
            for (int j = 0; j < 8; j++) {
                int nl = wn * 64 + j * 8 + l2;
#pragma unroll
                for (int e = 0; e < 4; e++) {
                    float v = acc[f][j][e] + ((e & 2) ? b1v : b0v);
                    v = fmaxf(v, 0.f);
                    sH[(nl + (e & 1)) * 130 + mb + ((e & 2) ? 8 : 0)] =
                        __half_as_ushort(__float2half(v));
                }
            }
        }
        __syncthreads();
#pragma unroll 8
        for (int t = 0; t < 64; t++) {
            int idx = tid + t * 256;
            int row = idx >> 7, ml = idx & 127;
            int ng = n0 + row;
            size_t pixpad = (size_t)(((ng >> 8) + 2) * PADW + (ng & 255) + 2) * 256 + m0 + ml;
            g_H[pixpad] = sH[row * 130 + ml];
        }
    } else {
        float* sF = (float*)smem;   // [m 128][pitch 130]
#pragma unroll
        for (int f = 0; f < 2; f++) {
            int mb = wm * 32 + f * 16 + l4;
            float b0v = bias[m0 + mb], b1v = bias[m0 + mb + 8];
#pragma unroll
            for (int j = 0; j < 8; j++) {
                int nl = wn * 64 + j * 8 + l2;
#pragma unroll
                for (int e = 0; e < 4; e++) {
                    float v = acc[f][j][e] + ((e & 2) ? b1v : b0v);
                    sF[(mb + ((e & 2) ? 8 : 0)) * 130 + nl + (e & 1)] = fmaxf(v, 0.f);
                }
            }
        }
        __syncthreads();
#pragma unroll 8
        for (int t = 0; t < 64; t++) {
            int idx = tid + t * 256;
            int ml = idx >> 7, nl = idx & 127;
            Out[(size_t)(m0 + ml) * P2 + n0 + nl] = sF[ml * 130 + nl];
        }
    }
}

// -------------------- conv2: fp16 1-term, B reused across dx ---------------
__global__ void __launch_bounds__(256, 1) k_conv2mma(const float* __restrict__ bias2)
{
    extern __shared__ __align__(1024) char smem[];
    uint32_t sb = smem_u32(smem);
    const int tid = threadIdx.x;
    const int lane = tid & 31, wid = tid >> 5;
    const int wm = wid >> 1, wn = wid & 1;
    const int bx = blockIdx.x;
    const int y = bx >> 1, x0 = (bx & 1) * 128;
    const int m0 = blockIdx.y * 128;
    const int pixbase = y * 256 + x0;

    const int rb = tid >> 3;
    const int cc = tid & 7;
    const char* WtB = (const char*)g_Wt;
    const char* HB  = (const char*)g_H;

    uint32_t aRow[2], aSw[2];
    const uint32_t aHi = lane >> 4;
#pragma unroll
    for (int f = 0; f < 2; f++) {
        int r = wm * 32 + f * 16 + (lane & 15);
        aRow[f] = r << 7;
        aSw[f] = r & 7;
    }
    uint32_t rB0[4];
    const uint32_t bHi = (lane >> 3) & 1;
#pragma unroll
    for (int g = 0; g < 4; g++)
        rB0[g] = wn * 64 + g * 16 + (lane & 7) + ((lane >> 4) << 3);

    float acc[2][8][4];
#pragma unroll
    for (int i = 0; i < 2; i++)
#pragma unroll
        for (int j = 0; j < 8; j++)
#pragma unroll
            for (int e = 0; e < 4; e++) acc[i][j][e] = 0.f;

    auto fill = [&](int it) {
        int dy = it / 20, rem = it % 20, chunk = rem / 5, dx = rem % 5;
        int tap = dy * 5 + dx;
        const char* srcA = WtB + (long)tap * 131072 + chunk * 128;
        uint32_t stgA = sb + (it % 3) * C2_A_STAGE;
#pragma unroll
        for (int t = 0; t < 4; t++) {
            int r = rb + 32 * t;
            uint32_t sw = (uint32_t)((cc ^ (r & 7)) << 4);
            long a0 = (long)(m0 + r) * 512 + cc * 16;
            cpa16(stgA + r * 128 + sw, srcA + a0);
        }
        if (dx == 0) {
            uint32_t stgB = sb + C2_B_OFF + ((it / 5) & 1) * C2_B_SLOT;
            const char* srcB = HB + (long)((y + dy) * PADW + x0) * 512 + chunk * 128;
            for (int o = tid * 16; o < C2_B_SLOT; o += 4096) {
                int r = o >> 7;
                int cB = o & 127;
                uint32_t sw = (uint32_t)(r * 128 + (cB ^ ((r & 7) << 4)));
                cpa16(stgB + sw, srcB + (long)r * 512 + cB);
            }
        }
        asm volatile("cp.async.commit_group;" ::: "memory");
    };

    fill(0);
    fill(1);

    for (int it = 0; it < 100; it++) {
        if (it == 99) asm volatile("cp.async.wait_group 0;" ::: "memory");
        else          asm volatile("cp.async.wait_group 1;" ::: "memory");
        __syncthreads();
        const int dxi = it % 5;
        uint32_t stgA = sb + (it % 3) * C2_A_STAGE;
        uint32_t stgB = sb + C2_B_OFF + ((it / 5) & 1) * C2_B_SLOT;
#pragma unroll
        for (int ks = 0; ks < 4; ks++) {
            uint32_t Wh[2][4], Bh[4][4];
#pragma unroll
            for (int f = 0; f < 2; f++) {
                uint32_t col = ((((uint32_t)(ks << 1) + aHi) ^ aSw[f]) << 4);
                ldsm4(Wh[f], stgA + aRow[f] + col);
            }
#pragma unroll
            for (int g = 0; g < 4; g++) {
                uint32_t rr = rB0[g] + dxi;
                uint32_t addr = stgB + (rr << 7)
                              + ((((uint32_t)(ks << 1) + bHi) ^ (rr & 7)) << 4);
                ldsm4(Bh[g], addr);
            }
#pragma unroll
            for (int f = 0; f < 2; f++)
#pragma unroll
                for (int g = 0; g < 4; g++)
#pragma unroll
                    for (int h = 0; h < 2; h++)
                        mma_f16(acc[f][g * 2 + h], Wh[f],
                                Bh[g][h * 2], Bh[g][h * 2 + 1]);
        }
        if (it + 2 < 100) fill(it + 2);
    }
    __syncthreads();

    // staged epilogue -> g_Ct px-major, coalesced
    const int l4 = lane >> 2, l2 = (lane & 3) * 2;
    float* sF = (float*)smem;   // [n 128][pitch 130]
#pragma unroll
    for (int f = 0; f < 2; f++) {
        int mb = wm * 32 + f * 16 + l4;
        float b0v = bias2[m0 + mb], b1v = bias2[m0 + mb + 8];
#pragma unroll
        for (int j = 0; j < 8; j++) {
            int nl = wn * 64 + j * 8 + l2;
#pragma unroll
            for (int e = 0; e < 4; e++) {
                float v = acc[f][j][e] + ((e & 2) ? b1v : b0v);
                sF[(nl + (e & 1)) * 130 + mb + ((e & 2) ? 8 : 0)] = fmaxf(v, 0.f);
            }
        }
    }
    __syncthreads();
#pragma unroll 8
    for (int t = 0; t < 64; t++) {
        int idx = tid + t * 256;
        int row = idx >> 7, ml = idx & 127;
        g_Ct[(size_t)(pixbase + row) * 256 + m0 + ml] = sF[row * 130 + ml];
    }
}

// -------------------- guided filter (px-major, wide kernels) ---------------
__global__ void k_gf_row1()
{
    int idx = blockIdx.x * blockDim.x + threadIdx.x;
    if (idx >= CE * P2) return;
    int c = idx & 255;
    int pp = idx >> 8;
    int y = pp >> 8, x = pp & 255;
    size_t rowbase = (size_t)(y * 256) * 256 + c;
    float sp = 0.f, sip = 0.f;
    for (int dxx = -2; dxx <= 2; dxx++) {
        int xx = x + dxx;
        if (xx < 0 || xx > 255) continue;
        float pv = g_Ct[rowbase + (size_t)xx * 256];
        sp  += pv;
        sip += pv * g_guide[y * 256 + xx];
    }
    g_D[idx] = sp;
    g_E[idx] = sip;
}

__global__ void k_gf_col1()
{
    int idx = blockIdx.x * blockDim.x + threadIdx.x;
    if (idx >= CE * P2) return;
    int pp = idx >> 8;
    int y = pp >> 8, x = pp & 255;
    float sp = 0.f, sip = 0.f;
    for (int dyy = -2; dyy <= 2; dyy++) {
        int yy = y + dyy;
        if (yy < 0 || yy > 255) continue;
        int off = idx + (dyy << 16);
        sp  += g_D[off];
        sip += g_E[off];
    }
    float inv = 1.f / (float)(cnt_axis(y) * cnt_axis(x));
    float mp  = sp * inv;
    float mIp = sip * inv;
    float mI  = g_meanI[pp];
    float a = (mIp - mI * mp) / (g_varI[pp] + EPS_GF);
    g_Aa[idx] = a;
    g_F[idx] = mp - a * mI;
}

__global__ void k_gf_row2()
{
    int idx = blockIdx.x * blockDim.x + threadIdx.x;
    if (idx >= CE * P2) return;
    int c = idx & 255;
    int pp = idx >> 8;
    int y = pp >> 8, x = pp & 255;
    size_t rowbase = (size_t)(y * 256) * 256 + c;
    float sa = 0.f, sb = 0.f;
    for (int dxx = -2; dxx <= 2; dxx++) {
        int xx = x + dxx;
        if (xx < 0 || xx > 255) continue;
        sa += g_Aa[rowbase + (size_t)xx * 256];
        sb += g_F [rowbase + (size_t)xx * 256];
    }
    g_D[idx] = sa;
    g_E[idx] = sb;
}

// col2 emits filt directly as fp16 into g_V (conv3 input)
__global__ void k_gf_col2()
{
    int idx = blockIdx.x * blockDim.x + threadIdx.x;
    if (idx >= CE * P2) return;
    int pp = idx >> 8;
    int y = pp >> 8, x = pp & 255;
    float sa = 0.f, sb = 0.f;
    for (int dyy = -2; dyy <= 2; dyy++) {
        int yy = y + dyy;
        if (yy < 0 || yy > 255) continue;
        int off = idx + (dyy << 16);
        sa += g_D[off];
        sb += g_E[off];
    }
    float inv = 1.f / (float)(cnt_axis(y) * cnt_axis(x));
    float filt = (sa * inv) * g_guide[pp] + sb * inv;
    g_V[idx] = __float2half(filt);
}

// -------------------- mask head --------------------------------------------
__global__ void k_maskhead(const float* __restrict__ featOut,
                           const float* __restrict__ wm,
                           const float* __restrict__ bm,
                           float* __restrict__ maskOut)
{
    __shared__ float sw[256];
    int tid = threadIdx.x;
    sw[tid] = wm[tid];
    __syncthreads();
    int p = blockIdx.x * blockDim.x + tid;
    if (p >= P2) return;
    float s = bm[0];
#pragma unroll 8
    for (int c = 0; c < 256; c++)
        s += sw[c] * featOut[(size_t)c * P2 + p];
    maskOut[p] = 1.f / (1.f + expf(-s));
}

// ---------------------------------------------------------------------------
extern "C" void kernel_launch(void* const* d_in, const int* in_sizes, int n_in,
                              void* d_out, int out_size)
{
    const float* fg   = (const float*)d_in[0];
    const float* bg   = (const float*)d_in[1];
    const float* mask = (const float*)d_in[2];
    const float* feat = (const float*)d_in[3];
    const float* w1   = (const float*)d_in[4];
    const float* b1   = (const float*)d_in[5];
    const float* w2   = (const float*)d_in[6];
    const float* b2   = (const float*)d_in[7];
    const float* w3   = (const float*)d_in[8];
    const float* b3   = (const float*)d_in[9];
    const float* wm   = (const float*)d_in[10];
    const float* bm   = (const float*)d_in[11];

    float* out     = (float*)d_out;
    float* maskOut = out;           // (1,1,256,256)
    float* featOut = out + P2;      // (1,256,256,256)

    const int T = 256;

    cudaFuncSetAttribute(k_conv2mma,
                         cudaFuncAttributeMaxDynamicSharedMemorySize, SMEM_C2);
    cudaFuncSetAttribute(k_mma1x1<5, 0>,
                         cudaFuncAttributeMaxDynamicSharedMemorySize, SMEM_1X1);
    cudaFuncSetAttribute(k_mma1x1<4, 1>,
                         cudaFuncAttributeMaxDynamicSharedMemorySize, SMEM_1X1);

    // weight preps (no deps)
    k_prepw <<<(WT_ELEMS + T - 1) / T, T>>>(w2);
    k_prepw1<<<(2 * 256 * K1PAD + T - 1) / T, T>>>(w1);
    k_prepw3<<<(2 * 256 * 256 + T - 1) / T, T>>>(w3);
    // 1. fused upsample + transpose -> g_U fp16
    k_upT<<<dim3(P2 / 32, K1PAD / 32), dim3(32, 8)>>>(fg, bg, mask, feat);
    // 2. guide + box statistics
    k_guide <<<(P2 + T - 1) / T, T>>>();
    k_istats<<<(P2 + T - 1) / T, T>>>();
    // 3. conv1 mma -> g_H (fp16 single plane)
    k_mma1x1<5, 0><<<dim3(512, 2), 256, SMEM_1X1>>>(b1, nullptr);
    // 4. conv2 mma (fp16 1-term) -> g_Ct
    k_conv2mma<<<dim3(512, 2), 256, SMEM_C2>>>(b2);
    // 5. guided filter; col2 writes conv3 input g_V fp16 directly
    int NB = (CE * P2 + T - 1) / T;
    k_gf_row1<<<NB, T>>>();
    k_gf_col1<<<NB, T>>>();
    k_gf_row2<<<NB, T>>>();
    k_gf_col2<<<NB, T>>>();
    // 6. conv3 mma -> featOut
    k_mma1x1<4, 1><<<dim3(512, 2), 256, SMEM_1X1>>>(b3, featOut);
    // 7. mask head
    k_maskhead<<<(P2 + T - 1) / T, T>>>(featOut, wm, bm, maskOut);
}

// round 14
// speedup vs baseline: 1.9049x; 1.0528x over previous
#include <cuda_runtime.h>
#include <cuda_bf16.h>
#include <cuda_fp16.h>
#include <math.h>
#include <stdint.h>

// ---------------------------------------------------------------------------
// GuidedUpsampleUnitGF — all convs single-term fp16 mma; GF mostly fp16
//   (E = I*p sums kept fp32: cancellation-sensitive — see error analysis)
// NOTE: __device__ globals must NEVER be passed as kernel args from host.
// ---------------------------------------------------------------------------

#define P2    65536
#define C_IN  263
#define CE    256
#define EPS_GF 0.01f

#define PADH 260
#define PADW 264
#define PADP (PADH * PADW)
#define HPLANE ((size_t)PADP * 256)

#define WT_ELEMS (25 * 256 * 256)

#define K1PAD 320
#define UPLANE ((size_t)P2 * K1PAD)
#define VPLANE ((size_t)P2 * 256)

// 1x1 conv smem: stage = A 16K + B 16K
#define STAGE_1X1 32768
#define SMEM_1X1 (3 * STAGE_1X1)   // 98304 (covers fp32 epilogue tile 66560)

// conv2 smem: A ring 3 x 16KB, B ring 2 x 16896 (132 rows x 128B)
#define C2_A_STAGE 16384
#define C2_B_OFF   49152
#define C2_B_SLOT  16896
#define SMEM_C2    (C2_B_OFF + 2 * C2_B_SLOT)   // 82944

// -------------------- scratch ----------------------------------------------
__device__ __align__(256) __half g_Ct[(size_t)P2 * 256]; // px-major conv2 out fp16
__device__ __align__(256) __half g_Aa[(size_t)P2 * 256]; // 'a'
__device__ __align__(256) __half g_D [(size_t)P2 * 256]; // p-rowsums / a-rowsums
__device__ __align__(256) float  g_E [(size_t)P2 * 256]; // I*p rowsums (fp32!)
__device__ __align__(256) __half g_Eh[(size_t)P2 * 256]; // b-rowsums (pass 2)
__device__ __align__(256) __half g_F [(size_t)P2 * 256]; // 'b'
__device__ __align__(256) float g_guide[P2];
__device__ __align__(256) float g_meanI[P2];
__device__ __align__(256) float g_varI[P2];
__device__ __align__(256) unsigned short g_H[HPLANE];   // conv1 out fp16, padded
__device__ __align__(256) __half g_Wt[WT_ELEMS];        // conv2 W fp16
__device__ __align__(256) __half g_U [UPLANE];          // conv1 input fp16
__device__ __align__(256) __half g_V [VPLANE];          // conv3 input fp16 (filt)
__device__ __align__(256) __half g_W1[256 * K1PAD];     // conv1 W fp16
__device__ __align__(256) __half g_W3[256 * 256];       // conv3 W fp16

// -------------------- helpers ----------------------------------------------
__device__ __forceinline__ uint32_t smem_u32(const void* p) {
    uint32_t a;
    asm("{ .reg .u64 t; cvta.to.shared.u64 t, %1; cvt.u32.u64 %0, t; }" : "=r"(a) : "l"(p));
    return a;
}
__device__ __forceinline__ void cpa16(uint32_t dst, const void* src) {
    asm volatile("cp.async.cg.shared.global [%0], [%1], 16;\n" :: "r"(dst), "l"(src));
}
__device__ __forceinline__ void ldsm4(uint32_t* r, uint32_t addr) {
    asm volatile("ldmatrix.sync.aligned.m8n8.x4.shared.b16 {%0,%1,%2,%3}, [%4];"
                 : "=r"(r[0]), "=r"(r[1]), "=r"(r[2]), "=r"(r[3]) : "r"(addr));
}
__device__ __forceinline__ void mma_f16(float* d, const uint32_t* a,
                                        uint32_t b0, uint32_t b1) {
    asm volatile("mma.sync.aligned.m16n8k16.row.col.f32.f16.f16.f32 "
                 "{%0,%1,%2,%3}, {%4,%5,%6,%7}, {%8,%9}, {%0,%1,%2,%3};"
                 : "+f"(d[0]), "+f"(d[1]), "+f"(d[2]), "+f"(d[3])
                 : "r"(a[0]), "r"(a[1]), "r"(a[2]), "r"(a[3]), "r"(b0), "r"(b1));
}

// -------------------- fused upsample + transpose -> g_U fp16 ----------------
__global__ void __launch_bounds__(256) k_upT(const float* __restrict__ fg,
                                             const float* __restrict__ bg,
                                             const float* __restrict__ mask,
                                             const float* __restrict__ feat)
{
    __shared__ float tile[32][33];
    const int p0 = blockIdx.x * 32;
    const int c0 = blockIdx.y * 32;
    const int tx = threadIdx.x, ty = threadIdx.y;

    int p = p0 + tx;
    int y = p >> 8, x = p & 255;
    float sy = 0.5f * (float)y - 0.25f;
    float sx = 0.5f * (float)x - 0.25f;
    float fy = sy - floorf(sy);
    float fx = sx - floorf(sx);
    int y0 = (int)floorf(sy);
    int x0 = (int)floorf(sx);
    int y0c = max(y0, 0),       x0c = max(x0, 0);
    int y1c = min(y0 + 1, 127), x1c = min(x0 + 1, 127);
    int i00 = y0c * 128 + x0c, i01 = y0c * 128 + x1c;
    int i10 = y1c * 128 + x0c, i11 = y1c * 128 + x1c;
    float w00 = (1.f - fy) * (1.f - fx), w01 = (1.f - fy) * fx;
    float w10 = fy * (1.f - fx),         w11 = fy * fx;

#pragma unroll
    for (int k = 0; k < 4; k++) {
        int ch = c0 + ty + k * 8;
        float v = 0.f;
        if (ch < C_IN) {
            const float* src;
            if (ch == 0)      src = mask;
            else if (ch <= 3) src = fg + (ch - 1) * 16384;
            else if (ch <= 6) src = bg + (ch - 4) * 16384;
            else              src = feat + (ch - 7) * 16384;
            v = w00 * src[i00] + w01 * src[i01] + w10 * src[i10] + w11 * src[i11];
        }
        tile[ty + k * 8][tx] = v;
    }
    __syncthreads();
#pragma unroll
    for (int k = 0; k < 4; k++) {
        int pp = p0 + ty + k * 8;
        int ch = c0 + tx;
        g_U[(size_t)pp * K1PAD + ch] = __float2half(tile[tx][ty + k * 8]);
    }
}

// guide from g_U fp16 (channels 1..3 = fg)
__global__ void k_guide()
{
    int p = blockIdx.x * blockDim.x + threadIdx.x;
    if (p >= P2) return;
    float s = __half2float(g_U[(size_t)p * K1PAD + 1])
            + __half2float(g_U[(size_t)p * K1PAD + 2])
            + __half2float(g_U[(size_t)p * K1PAD + 3]);
    g_guide[p] = s * (128.0f / 3.0f);
}

__device__ __forceinline__ int cnt_axis(int i)
{
    return min(i + 2, 255) - max(i - 2, 0) + 1;
}

__global__ void k_istats()
{
    int p = blockIdx.x * blockDim.x + threadIdx.x;
    if (p >= P2) return;
    int y = p >> 8, x = p & 255;
    float sI = 0.f, sI2 = 0.f;
    for (int dy = -2; dy <= 2; dy++) {
        int yy = y + dy;
        if (yy < 0 || yy > 255) continue;
        for (int dx = -2; dx <= 2; dx++) {
            int xx = x + dx;
            if (xx < 0 || xx > 255) continue;
            float v = g_guide[yy * 256 + xx];
            sI += v; sI2 += v * v;
        }
    }
    float inv = 1.f / (float)(cnt_axis(y) * cnt_axis(x));
    float mI = sI * inv;
    g_meanI[p] = mI;
    g_varI[p]  = sI2 * inv - mI * mI;
}

// -------------------- weight prep kernels (single fp16 planes) --------------
__global__ void k_prepw(const float* __restrict__ w2)
{
    int idx = blockIdx.x * blockDim.x + threadIdx.x;
    if (idx >= WT_ELEMS) return;
    int ch = idx & 255;
    int m  = (idx >> 8) & 255;
    int tap = idx >> 16;
    g_Wt[idx] = __float2half(w2[(size_t)m * 6400 + ch * 25 + tap]);
}

__global__ void k_prepw1(const float* __restrict__ w1)
{
    int idx = blockIdx.x * blockDim.x + threadIdx.x;
    if (idx >= 256 * K1PAD) return;
    int ch = idx % K1PAD;
    int m  = idx / K1PAD;
    g_W1[idx] = __float2half((ch < C_IN) ? w1[(size_t)m * C_IN + ch] : 0.f);
}

__global__ void k_prepw3(const float* __restrict__ w3)
{
    int idx = blockIdx.x * blockDim.x + threadIdx.x;
    if (idx >= 256 * 256) return;
    g_W3[idx] = __float2half(w3[idx]);
}

// -------------------- generic 1x1 conv MMA (fp16 1-term) --------------------
// MODE 0: A=g_W1, B=g_U, epilogue -> g_H fp16 single plane, padded px-major
// MODE 1: A=g_W3, B=g_V, epilogue -> Out fp32 ch-major (conv3)
template<int NKC, int MODE>
__global__ void __launch_bounds__(256, 1) k_mma1x1(const float* __restrict__ bias,
                                                   float* __restrict__ Out)
{
    constexpr int KPAD = NKC * 64;

    extern __shared__ __align__(1024) char smem[];
    uint32_t sb = smem_u32(smem);
    const int tid = threadIdx.x;
    const int lane = tid & 31, wid = tid >> 5;
    const int wm = wid >> 1, wn = wid & 1;
    const int n0 = blockIdx.x * 128;
    const int m0 = blockIdx.y * 128;

    const int rb = tid >> 3;
    const int cc = tid & 7;
    const char* AB = (MODE == 0) ? (const char*)g_W1 : (const char*)g_W3;
    const char* BB = (MODE == 0) ? (const char*)g_U  : (const char*)g_V;

    uint32_t aRow[2], aSw[2];
    const uint32_t aHi = lane >> 4;
#pragma unroll
    for (int f = 0; f < 2; f++) {
        int r = wm * 32 + f * 16 + (lane & 15);
        aRow[f] = r << 7;
        aSw[f] = r & 7;
    }
    uint32_t bRow[4], bSw[4];
    const uint32_t bHi = (lane >> 3) & 1;
#pragma unroll
    for (int g = 0; g < 4; g++) {
        int r = wn * 64 + g * 16 + (lane & 7) + ((lane >> 4) << 3);
        bRow[g] = r << 7;
        bSw[g] = r & 7;
    }

    float acc[2][8][4];
#pragma unroll
    for (int i = 0; i < 2; i++)
#pragma unroll
        for (int j = 0; j < 8; j++)
#pragma unroll
            for (int e = 0; e < 4; e++) acc[i][j][e] = 0.f;

    auto fill = [&](int it) {
        uint32_t stg = sb + (it % 3) * STAGE_1X1;
        long kO = (long)it * 128;
#pragma unroll
        for (int t = 0; t < 4; t++) {
            int r = rb + 32 * t;
            uint32_t sw = (uint32_t)((cc ^ (r & 7)) << 4);
            long a0 = (long)(m0 + r) * (KPAD * 2) + kO + cc * 16;
            cpa16(stg + r * 128 + sw, AB + a0);
            long b0 = (long)(n0 + r) * (KPAD * 2) + kO + cc * 16;
            cpa16(stg + 16384 + r * 128 + sw, BB + b0);
        }
        asm volatile("cp.async.commit_group;" ::: "memory");
    };

    fill(0);
    fill(1);

    for (int it = 0; it < NKC; it++) {
        if (it == NKC - 1) asm volatile("cp.async.wait_group 0;" ::: "memory");
        else               asm volatile("cp.async.wait_group 1;" ::: "memory");
        __syncthreads();
        uint32_t stg = sb + (it % 3) * STAGE_1X1;
#pragma unroll
        for (int ks = 0; ks < 4; ks++) {
            uint32_t Wh[2][4], Bh[4][4];
#pragma unroll
            for (int f = 0; f < 2; f++) {
                uint32_t col = ((((uint32_t)(ks << 1) + aHi) ^ aSw[f]) << 4);
                ldsm4(Wh[f], stg + aRow[f] + col);
            }
#pragma unroll
            for (int g = 0; g < 4; g++) {
                uint32_t col = ((((uint32_t)(ks << 1) + bHi) ^ bSw[g]) << 4);
                ldsm4(Bh[g], stg + 16384 + bRow[g] + col);
            }
#pragma unroll
            for (int f = 0; f < 2; f++)
#pragma unroll
                for (int g = 0; g < 4; g++)
#pragma unroll
                    for (int h = 0; h < 2; h++)
                        mma_f16(acc[f][g * 2 + h], Wh[f],
                                Bh[g][h * 2], Bh[g][h * 2 + 1]);
        }
        if (it + 2 < NKC) fill(it + 2);
    }
    __syncthreads();

    // ---- staged epilogue ----
    const int l4 = lane >> 2, l2 = (lane & 3) * 2;
    if (MODE == 0) {
        unsigned short* sH = (unsigned short*)smem;   // [n 128][pitch 130] fp16
#pragma unroll
        for (int f = 0; f < 2; f++) {
            int mb = wm * 32 + f * 16 + l4;
            float b0v = bias[m0 + mb], b1v = bias[m0 + mb + 8];
#pragma unroll
            for (int j = 0; j < 8; j++) {
                int nl = wn * 64 + j * 8 + l2;
#pragma unroll
                for (int e = 0; e < 4; e++) {
                    float v = acc[f][j][e] + ((e & 2) ? b1v : b0v);
                    v = fmaxf(v, 0.f);
                    sH[(nl + (e & 1)) * 130 + mb + ((e & 2) ? 8 : 0)] =
                        __half_as_ushort(__float2half(v));
                }
            }
        }
        __syncthreads();
#pragma unroll 8
        for (int t = 0; t < 64; t++) {
            int idx = tid + t * 256;
            int row = idx >> 7, ml = idx & 127;
            int ng = n0 + row;
            size_t pixpad = (size_t)(((ng >> 8) + 2) * PADW + (ng & 255) + 2) * 256 + m0 + ml;
            g_H[pixpad] = sH[row * 130 + ml];
        }
    } else {
        float* sF = (float*)smem;   // [m 128][pitch 130]
#pragma unroll
        for (int f = 0; f < 2; f++) {
            int mb = wm * 32 + f * 16 + l4;
            float b0v = bias[m0 + mb], b1v = bias[m0 + mb + 8];
#pragma unroll
            for (int j = 0; j < 8; j++) {
                int nl = wn * 64 + j * 8 + l2;
#pragma unroll
                for (int e = 0; e < 4; e++) {
                    float v = acc[f][j][e] + ((e & 2) ? b1v : b0v);
                    sF[(mb + ((e & 2) ? 8 : 0)) * 130 + nl + (e & 1)] = fmaxf(v, 0.f);
                }
            }
        }
        __syncthreads();
#pragma unroll 8
        for (int t = 0; t < 64; t++) {
            int idx = tid + t * 256;
            int ml = idx >> 7, nl = idx & 127;
            Out[(size_t)(m0 + ml) * P2 + n0 + nl] = sF[ml * 130 + nl];
        }
    }
}

// -------------------- conv2: fp16 1-term, B reused across dx ---------------
__global__ void __launch_bounds__(256, 1) k_conv2mma(const float* __restrict__ bias2)
{
    extern __shared__ __align__(1024) char smem[];
    uint32_t sb = smem_u32(smem);
    const int tid = threadIdx.x;
    const int lane = tid & 31, wid = tid >> 5;
    const int wm = wid >> 1, wn = wid & 1;
    const int bx = blockIdx.x;
    const int y = bx >> 1, x0 = (bx & 1) * 128;
    const int m0 = blockIdx.y * 128;
    const int pixbase = y * 256 + x0;

    const int rb = tid >> 3;
    const int cc = tid & 7;
    const char* WtB = (const char*)g_Wt;
    const char* HB  = (const char*)g_H;

    uint32_t aRow[2], aSw[2];
    const uint32_t aHi = lane >> 4;
#pragma unroll
    for (int f = 0; f < 2; f++) {
        int r = wm * 32 + f * 16 + (lane & 15);
        aRow[f] = r << 7;
        aSw[f] = r & 7;
    }
    uint32_t rB0[4];
    const uint32_t bHi = (lane >> 3) & 1;
#pragma unroll
    for (int g = 0; g < 4; g++)
        rB0[g] = wn * 64 + g * 16 + (lane & 7) + ((lane >> 4) << 3);

    float acc[2][8][4];
#pragma unroll
    for (int i = 0; i < 2; i++)
#pragma unroll
        for (int j = 0; j < 8; j++)
#pragma unroll
            for (int e = 0; e < 4; e++) acc[i][j][e] = 0.f;

    auto fill = [&](int it) {
        int dy = it / 20, rem = it % 20, chunk = rem / 5, dx = rem % 5;
        int tap = dy * 5 + dx;
        const char* srcA = WtB + (long)tap * 131072 + chunk * 128;
        uint32_t stgA = sb + (it % 3) * C2_A_STAGE;
#pragma unroll
        for (int t = 0; t < 4; t++) {
            int r = rb + 32 * t;
            uint32_t sw = (uint32_t)((cc ^ (r & 7)) << 4);
            long a0 = (long)(m0 + r) * 512 + cc * 16;
            cpa16(stgA + r * 128 + sw, srcA + a0);
        }
        if (dx == 0) {
            uint32_t stgB = sb + C2_B_OFF + ((it / 5) & 1) * C2_B_SLOT;
            const char* srcB = HB + (long)((y + dy) * PADW + x0) * 512 + chunk * 128;
            for (int o = tid * 16; o < C2_B_SLOT; o += 4096) {
                int r = o >> 7;
                int cB = o & 127;
                uint32_t sw = (uint32_t)(r * 128 + (cB ^ ((r & 7) << 4)));
                cpa16(stgB + sw, srcB + (long)r * 512 + cB);
            }
        }
        asm volatile("cp.async.commit_group;" ::: "memory");
    };

    fill(0);
    fill(1);

    for (int it = 0; it < 100; it++) {
        if (it == 99) asm volatile("cp.async.wait_group 0;" ::: "memory");
        else          asm volatile("cp.async.wait_group 1;" ::: "memory");
        __syncthreads();
        const int dxi = it % 5;
        uint32_t stgA = sb + (it % 3) * C2_A_STAGE;
        uint32_t stgB = sb + C2_B_OFF + ((it / 5) & 1) * C2_B_SLOT;
#pragma unroll
        for (int ks = 0; ks < 4; ks++) {
            uint32_t Wh[2][4], Bh[4][4];
#pragma unroll
            for (int f = 0; f < 2; f++) {
                uint32_t col = ((((uint32_t)(ks << 1) + aHi) ^ aSw[f]) << 4);
                ldsm4(Wh[f], stgA + aRow[f] + col);
            }
#pragma unroll
            for (int g = 0; g < 4; g++) {
                uint32_t rr = rB0[g] + dxi;
                uint32_t addr = stgB + (rr << 7)
                              + ((((uint32_t)(ks << 1) + bHi) ^ (rr & 7)) << 4);
                ldsm4(Bh[g], addr);
            }
#pragma unroll
            for (int f = 0; f < 2; f++)
#pragma unroll
                for (int g = 0; g < 4; g++)
#pragma unroll
                    for (int h = 0; h < 2; h++)
                        mma_f16(acc[f][g * 2 + h], Wh[f],
                                Bh[g][h * 2], Bh[g][h * 2 + 1]);
        }
        if (it + 2 < 100) fill(it + 2);
    }
    __syncthreads();

    // staged epilogue -> g_Ct fp16 px-major, coalesced
    const int l4 = lane >> 2, l2 = (lane & 3) * 2;
    unsigned short* sH = (unsigned short*)smem;   // [n 128][pitch 130]
#pragma unroll
    for (int f = 0; f < 2; f++) {
        int mb = wm * 32 + f * 16 + l4;
        float b0v = bias2[m0 + mb], b1v = bias2[m0 + mb + 8];
#pragma unroll
        for (int j = 0; j < 8; j++) {
            int nl = wn * 64 + j * 8 + l2;
#pragma unroll
            for (int e = 0; e < 4; e++) {
                float v = acc[f][j][e] + ((e & 2) ? b1v : b0v);
                sH[(nl + (e & 1)) * 130 + mb + ((e & 2) ? 8 : 0)] =
                    __half_as_ushort(__float2half(fmaxf(v, 0.f)));
            }
        }
    }
    __syncthreads();
#pragma unroll 8
    for (int t = 0; t < 64; t++) {
        int idx = tid + t * 256;
        int row = idx >> 7, ml = idx & 127;
        g_Ct[(size_t)(pixbase + row) * 256 + m0 + ml] =
            __ushort_as_half(sH[row * 130 + ml]);
    }
}

// -------------------- guided filter (px-major, wide kernels) ---------------
// pass 1 rows: D(h) = rowsum(p), E(f32) = rowsum(I*p)
__global__ void k_gf_row1()
{
    int idx = blockIdx.x * blockDim.x + threadIdx.x;
    if (idx >= CE * P2) return;
    int c = idx & 255;
    int pp = idx >> 8;
    int y = pp >> 8, x = pp & 255;
    size_t rowbase = (size_t)(y * 256) * 256 + c;
    float sp = 0.f, sip = 0.f;
    for (int dxx = -2; dxx <= 2; dxx++) {
        int xx = x + dxx;
        if (xx < 0 || xx > 255) continue;
        float pv = __half2float(g_Ct[rowbase + (size_t)xx * 256]);
        sp  += pv;
        sip += pv * g_guide[y * 256 + xx];
    }
    g_D[idx] = __float2half(sp);
    g_E[idx] = sip;
}

__global__ void k_gf_col1()
{
    int idx = blockIdx.x * blockDim.x + threadIdx.x;
    if (idx >= CE * P2) return;
    int pp = idx >> 8;
    int y = pp >> 8, x = pp & 255;
    float sp = 0.f, sip = 0.f;
    for (int dyy = -2; dyy <= 2; dyy++) {
        int yy = y + dyy;
        if (yy < 0 || yy > 255) continue;
        int off = idx + (dyy << 16);
        sp  += __half2float(g_D[off]);
        sip += g_E[off];
    }
    float inv = 1.f / (float)(cnt_axis(y) * cnt_axis(x));
    float mp  = sp * inv;
    float mIp = sip * inv;
    float mI  = g_meanI[pp];
    float a = (mIp - mI * mp) / (g_varI[pp] + EPS_GF);
    g_Aa[idx] = __float2half(a);
    g_F[idx]  = __float2half(mp - a * mI);
}

// pass 2 rows: D(h) = rowsum(a), Eh(h) = rowsum(b)
__global__ void k_gf_row2()
{
    int idx = blockIdx.x * blockDim.x + threadIdx.x;
    if (idx >= CE * P2) return;
    int c = idx & 255;
    int pp = idx >> 8;
    int y = pp >> 8, x = pp & 255;
    size_t rowbase = (size_t)(y * 256) * 256 + c;
    float sa = 0.f, sb = 0.f;
    for (int dxx = -2; dxx <= 2; dxx++) {
        int xx = x + dxx;
        if (xx < 0 || xx > 255) continue;
        sa += __half2float(g_Aa[rowbase + (size_t)xx * 256]);
        sb += __half2float(g_F [rowbase + (size_t)xx * 256]);
    }
    g_D[idx]  = __float2half(sa);
    g_Eh[idx] = __float2half(sb);
}

// col2 emits filt directly as fp16 into g_V (conv3 input)
__global__ void k_gf_col2()
{
    int idx = blockIdx.x * blockDim.x + threadIdx.x;
    if (idx >= CE * P2) return;
    int pp = idx >> 8;
    int y = pp >> 8, x = pp & 255;
    float sa = 0.f, sb = 0.f;
    for (int dyy = -2; dyy <= 2; dyy++) {
        int yy = y + dyy;
        if (yy < 0 || yy > 255) continue;
        int off = idx + (dyy << 16);
        sa += __half2float(g_D[off]);
        sb += __half2float(g_Eh[off]);
    }
    float inv = 1.f / (float)(cnt_axis(y) * cnt_axis(x));
    float filt = (sa * inv) * g_guide[pp] + sb * inv;
    g_V[idx] = __float2half(filt);
}

// -------------------- mask head --------------------------------------------
__global__ void k_maskhead(const float* __restrict__ featOut,
                           const float* __restrict__ wm,
                           const float* __restrict__ bm,
                           float* __restrict__ maskOut)
{
    __shared__ float sw[256];
    int tid = threadIdx.x;
    sw[tid] = wm[tid];
    __syncthreads();
    int p = blockIdx.x * blockDim.x + tid;
    if (p >= P2) return;
    float s = bm[0];
#pragma unroll 8
    for (int c = 0; c < 256; c++)
        s += sw[c] * featOut[(size_t)c * P2 + p];
    maskOut[p] = 1.f / (1.f + expf(-s));
}

// ---------------------------------------------------------------------------
extern "C" void kernel_launch(void* const* d_in, const int* in_sizes, int n_in,
                              void* d_out, int out_size)
{
    const float* fg   = (const float*)d_in[0];
    const float* bg   = (const float*)d_in[1];
    const float* mask = (const float*)d_in[2];
    const float* feat = (const float*)d_in[3];
    const float* w1   = (const float*)d_in[4];
    const float* b1   = (const float*)d_in[5];
    const float* w2   = (const float*)d_in[6];
    const float* b2   = (const float*)d_in[7];
    const float* w3   = (const float*)d_in[8];
    const float* b3   = (const float*)d_in[9];
    const float* wm   = (const float*)d_in[10];
    const float* bm   = (const float*)d_in[11];

    float* out     = (float*)d_out;
    float* maskOut = out;           // (1,1,256,256)
    float* featOut = out + P2;      // (1,256,256,256)

    const int T = 256;

    cudaFuncSetAttribute(k_conv2mma,
                         cudaFuncAttributeMaxDynamicSharedMemorySize, SMEM_C2);
    cudaFuncSetAttribute(k_mma1x1<5, 0>,
                         cudaFuncAttributeMaxDynamicSharedMemorySize, SMEM_1X1);
    cudaFuncSetAttribute(k_mma1x1<4, 1>,
                         cudaFuncAttributeMaxDynamicSharedMemorySize, SMEM_1X1);

    // weight preps (no deps)
    k_prepw <<<(WT_ELEMS + T - 1) / T, T>>>(w2);
    k_prepw1<<<(256 * K1PAD + T - 1) / T, T>>>(w1);
    k_prepw3<<<(256 * 256 + T - 1) / T, T>>>(w3);
    // 1. fused upsample + transpose -> g_U fp16
    k_upT<<<dim3(P2 / 32, K1PAD / 32), dim3(32, 8)>>>(fg, bg, mask, feat);
    // 2. guide + box statistics
    k_guide <<<(P2 + T - 1) / T, T>>>();
    k_istats<<<(P2 + T - 1) / T, T>>>();
    // 3. conv1 mma -> g_H (fp16 single plane)
    k_mma1x1<5, 0><<<dim3(512, 2), 256, SMEM_1X1>>>(b1, nullptr);
    // 4. conv2 mma (fp16 1-term) -> g_Ct fp16
    k_conv2mma<<<dim3(512, 2), 256, SMEM_C2>>>(b2);
    // 5. guided filter (fp16 storage, E fp32); col2 writes g_V fp16
    int NB = (CE * P2 + T - 1) / T;
    k_gf_row1<<<NB, T>>>();
    k_gf_col1<<<NB, T>>>();
    k_gf_row2<<<NB, T>>>();
    k_gf_col2<<<NB, T>>>();
    // 6. conv3 mma -> featOut
    k_mma1x1<4, 1><<<dim3(512, 2), 256, SMEM_1X1>>>(b3, featOut);
    // 7. mask head
    k_maskhead<<<(P2 + T - 1) / T, T>>>(featOut, wm, bm, maskOut);
}

// round 15
// speedup vs baseline: 2.1693x; 1.1388x over previous
#include <cuda_runtime.h>
#include <cuda_bf16.h>
#include <cuda_fp16.h>
#include <math.h>
#include <stdint.h>

// ---------------------------------------------------------------------------
// GuidedUpsampleUnitGF — all convs single-term fp16 mma; GF fp16 (E fp32)
//   conv3 epilogue fuses mask-head partial dot; guide fused into upsample.
// NOTE: __device__ globals must NEVER be passed as kernel args from host.
// ---------------------------------------------------------------------------

#define P2    65536
#define C_IN  263
#define CE    256
#define EPS_GF 0.01f

#define PADH 260
#define PADW 264
#define PADP (PADH * PADW)
#define HPLANE ((size_t)PADP * 256)

#define WT_ELEMS (25 * 256 * 256)

#define K1PAD 320
#define UPLANE ((size_t)P2 * K1PAD)
#define VPLANE ((size_t)P2 * 256)

// 1x1 conv smem: stage = A 16K + B 16K
#define STAGE_1X1 32768
#define SMEM_1X1 (3 * STAGE_1X1)   // 98304 (covers fp32 epilogue tile 66560)

// conv2 smem: A ring 3 x 16KB, B ring 2 x 16896 (132 rows x 128B)
#define C2_A_STAGE 16384
#define C2_B_OFF   49152
#define C2_B_SLOT  16896
#define SMEM_C2    (C2_B_OFF + 2 * C2_B_SLOT)   // 82944

// -------------------- scratch ----------------------------------------------
__device__ __align__(256) __half g_Ct[(size_t)P2 * 256]; // px-major conv2 out fp16
__device__ __align__(256) __half g_Aa[(size_t)P2 * 256]; // 'a'
__device__ __align__(256) __half g_D [(size_t)P2 * 256]; // p-rowsums / a-rowsums
__device__ __align__(256) float  g_E [(size_t)P2 * 256]; // I*p rowsums (fp32!)
__device__ __align__(256) __half g_Eh[(size_t)P2 * 256]; // b-rowsums (pass 2)
__device__ __align__(256) __half g_F [(size_t)P2 * 256]; // 'b'
__device__ __align__(256) float g_guide[P2];
__device__ __align__(256) float g_meanI[P2];
__device__ __align__(256) float g_varI[P2];
__device__ __align__(256) float g_MaskPart[2 * P2];     // conv3 mask partials
__device__ __align__(256) unsigned short g_H[HPLANE];   // conv1 out fp16, padded
__device__ __align__(256) __half g_Wt[WT_ELEMS];        // conv2 W fp16
__device__ __align__(256) __half g_U [UPLANE];          // conv1 input fp16
__device__ __align__(256) __half g_V [VPLANE];          // conv3 input fp16 (filt)
__device__ __align__(256) __half g_W1[256 * K1PAD];     // conv1 W fp16
__device__ __align__(256) __half g_W3[256 * 256];       // conv3 W fp16

// -------------------- helpers ----------------------------------------------
__device__ __forceinline__ uint32_t smem_u32(const void* p) {
    uint32_t a;
    asm("{ .reg .u64 t; cvta.to.shared.u64 t, %1; cvt.u32.u64 %0, t; }" : "=r"(a) : "l"(p));
    return a;
}
__device__ __forceinline__ void cpa16(uint32_t dst, const void* src) {
    asm volatile("cp.async.cg.shared.global [%0], [%1], 16;\n" :: "r"(dst), "l"(src));
}
__device__ __forceinline__ void ldsm4(uint32_t* r, uint32_t addr) {
    asm volatile("ldmatrix.sync.aligned.m8n8.x4.shared.b16 {%0,%1,%2,%3}, [%4];"
                 : "=r"(r[0]), "=r"(r[1]), "=r"(r[2]), "=r"(r[3]) : "r"(addr));
}
__device__ __forceinline__ void mma_f16(float* d, const uint32_t* a,
                                        uint32_t b0, uint32_t b1) {
    asm volatile("mma.sync.aligned.m16n8k16.row.col.f32.f16.f16.f32 "
                 "{%0,%1,%2,%3}, {%4,%5,%6,%7}, {%8,%9}, {%0,%1,%2,%3};"
                 : "+f"(d[0]), "+f"(d[1]), "+f"(d[2]), "+f"(d[3])
                 : "r"(a[0]), "r"(a[1]), "r"(a[2]), "r"(a[3]), "r"(b0), "r"(b1));
}

// -------------------- fused upsample + transpose + guide -> g_U fp16 --------
__global__ void __launch_bounds__(256) k_upT(const float* __restrict__ fg,
                                             const float* __restrict__ bg,
                                             const float* __restrict__ mask,
                                             const float* __restrict__ feat)
{
    __shared__ float tile[32][33];
    const int p0 = blockIdx.x * 32;
    const int c0 = blockIdx.y * 32;
    const int tx = threadIdx.x, ty = threadIdx.y;

    int p = p0 + tx;
    int y = p >> 8, x = p & 255;
    float sy = 0.5f * (float)y - 0.25f;
    float sx = 0.5f * (float)x - 0.25f;
    float fy = sy - floorf(sy);
    float fx = sx - floorf(sx);
    int y0 = (int)floorf(sy);
    int x0 = (int)floorf(sx);
    int y0c = max(y0, 0),       x0c = max(x0, 0);
    int y1c = min(y0 + 1, 127), x1c = min(x0 + 1, 127);
    int i00 = y0c * 128 + x0c, i01 = y0c * 128 + x1c;
    int i10 = y1c * 128 + x0c, i11 = y1c * 128 + x1c;
    float w00 = (1.f - fy) * (1.f - fx), w01 = (1.f - fy) * fx;
    float w10 = fy * (1.f - fx),         w11 = fy * fx;

#pragma unroll
    for (int k = 0; k < 4; k++) {
        int ch = c0 + ty + k * 8;
        float v = 0.f;
        if (ch < C_IN) {
            const float* src;
            if (ch == 0)      src = mask;
            else if (ch <= 3) src = fg + (ch - 1) * 16384;
            else if (ch <= 6) src = bg + (ch - 4) * 16384;
            else              src = feat + (ch - 7) * 16384;
            v = w00 * src[i00] + w01 * src[i01] + w10 * src[i10] + w11 * src[i11];
        }
        tile[ty + k * 8][tx] = v;
    }
    __syncthreads();
    // guide from fg channels (only c-block 0 holds them)
    if (c0 == 0 && ty == 0)
        g_guide[p0 + tx] = (tile[1][tx] + tile[2][tx] + tile[3][tx]) * (128.0f / 3.0f);
#pragma unroll
    for (int k = 0; k < 4; k++) {
        int pp = p0 + ty + k * 8;
        int ch = c0 + tx;
        g_U[(size_t)pp * K1PAD + ch] = __float2half(tile[tx][ty + k * 8]);
    }
}

__device__ __forceinline__ int cnt_axis(int i)
{
    return min(i + 2, 255) - max(i - 2, 0) + 1;
}

__global__ void k_istats()
{
    int p = blockIdx.x * blockDim.x + threadIdx.x;
    if (p >= P2) return;
    int y = p >> 8, x = p & 255;
    float sI = 0.f, sI2 = 0.f;
    for (int dy = -2; dy <= 2; dy++) {
        int yy = y + dy;
        if (yy < 0 || yy > 255) continue;
        for (int dx = -2; dx <= 2; dx++) {
            int xx = x + dx;
            if (xx < 0 || xx > 255) continue;
            float v = g_guide[yy * 256 + xx];
            sI += v; sI2 += v * v;
        }
    }
    float inv = 1.f / (float)(cnt_axis(y) * cnt_axis(x));
    float mI = sI * inv;
    g_meanI[p] = mI;
    g_varI[p]  = sI2 * inv - mI * mI;
}

// -------------------- weight prep kernels (single fp16 planes) --------------
__global__ void k_prepw(const float* __restrict__ w2)
{
    int idx = blockIdx.x * blockDim.x + threadIdx.x;
    if (idx >= WT_ELEMS) return;
    int ch = idx & 255;
    int m  = (idx >> 8) & 255;
    int tap = idx >> 16;
    g_Wt[idx] = __float2half(w2[(size_t)m * 6400 + ch * 25 + tap]);
}

__global__ void k_prepw1(const float* __restrict__ w1)
{
    int idx = blockIdx.x * blockDim.x + threadIdx.x;
    if (idx >= 256 * K1PAD) return;
    int ch = idx % K1PAD;
    int m  = idx / K1PAD;
    g_W1[idx] = __float2half((ch < C_IN) ? w1[(size_t)m * C_IN + ch] : 0.f);
}

__global__ void k_prepw3(const float* __restrict__ w3)
{
    int idx = blockIdx.x * blockDim.x + threadIdx.x;
    if (idx >= 256 * 256) return;
    g_W3[idx] = __float2half(w3[idx]);
}

// -------------------- generic 1x1 conv MMA (fp16 1-term) --------------------
// MODE 0: A=g_W1, B=g_U, epilogue -> g_H fp16 single plane, padded px-major
// MODE 1: A=g_W3, B=g_V, epilogue -> Out fp32 ch-major + mask partial dot
template<int NKC, int MODE>
__global__ void __launch_bounds__(256, 2) k_mma1x1(const float* __restrict__ bias,
                                                   const float* __restrict__ wm,
                                                   float* __restrict__ Out)
{
    constexpr int KPAD = NKC * 64;

    extern __shared__ __align__(1024) char smem[];
    uint32_t sb = smem_u32(smem);
    const int tid = threadIdx.x;
    const int lane = tid & 31, wid = tid >> 5;
    const int wm_ = wid >> 1, wn = wid & 1;
    const int n0 = blockIdx.x * 128;
    const int m0 = blockIdx.y * 128;

    const int rb = tid >> 3;
    const int cc = tid & 7;
    const char* AB = (MODE == 0) ? (const char*)g_W1 : (const char*)g_W3;
    const char* BB = (MODE == 0) ? (const char*)g_U  : (const char*)g_V;

    uint32_t aRow[2], aSw[2];
    const uint32_t aHi = lane >> 4;
#pragma unroll
    for (int f = 0; f < 2; f++) {
        int r = wm_ * 32 + f * 16 + (lane & 15);
        aRow[f] = r << 7;
        aSw[f] = r & 7;
    }
    uint32_t bRow[4], bSw[4];
    const uint32_t bHi = (lane >> 3) & 1;
#pragma unroll
    for (int g = 0; g < 4; g++) {
        int r = wn * 64 + g * 16 + (lane & 7) + ((lane >> 4) << 3);
        bRow[g] = r << 7;
        bSw[g] = r & 7;
    }

    float acc[2][8][4];
#pragma unroll
    for (int i = 0; i < 2; i++)
#pragma unroll
        for (int j = 0; j < 8; j++)
#pragma unroll
            for (int e = 0; e < 4; e++) acc[i][j][e] = 0.f;

    auto fill = [&](int it) {
        uint32_t stg = sb + (it % 3) * STAGE_1X1;
        long kO = (long)it * 128;
#pragma unroll
        for (int t = 0; t < 4; t++) {
            int r = rb + 32 * t;
            uint32_t sw = (uint32_t)((cc ^ (r & 7)) << 4);
            long a0 = (long)(m0 + r) * (KPAD * 2) + kO + cc * 16;
            cpa16(stg + r * 128 + sw, AB + a0);
            long b0 = (long)(n0 + r) * (KPAD * 2) + kO + cc * 16;
            cpa16(stg + 16384 + r * 128 + sw, BB + b0);
        }
        asm volatile("cp.async.commit_group;" ::: "memory");
    };

    fill(0);
    fill(1);

    for (int it = 0; it < NKC; it++) {
        if (it == NKC - 1) asm volatile("cp.async.wait_group 0;" ::: "memory");
        else               asm volatile("cp.async.wait_group 1;" ::: "memory");
        __syncthreads();
        uint32_t stg = sb + (it % 3) * STAGE_1X1;
#pragma unroll
        for (int ks = 0; ks < 4; ks++) {
            uint32_t Wh[2][4], Bh[4][4];
#pragma unroll
            for (int f = 0; f < 2; f++) {
                uint32_t col = ((((uint32_t)(ks << 1) + aHi) ^ aSw[f]) << 4);
                ldsm4(Wh[f], stg + aRow[f] + col);
            }
#pragma unroll
            for (int g = 0; g < 4; g++) {
                uint32_t col = ((((uint32_t)(ks << 1) + bHi) ^ bSw[g]) << 4);
                ldsm4(Bh[g], stg + 16384 + bRow[g] + col);
            }
#pragma unroll
            for (int f = 0; f < 2; f++)
#pragma unroll
                for (int g = 0; g < 4; g++)
#pragma unroll
                    for (int h = 0; h < 2; h++)
                        mma_f16(acc[f][g * 2 + h], Wh[f],
                                Bh[g][h * 2], Bh[g][h * 2 + 1]);
        }
        if (it + 2 < NKC) fill(it + 2);
    }
    __syncthreads();

    // ---- staged epilogue ----
    const int l4 = lane >> 2, l2 = (lane & 3) * 2;
    if (MODE == 0) {
        unsigned short* sH = (unsigned short*)smem;   // [n 128][pitch 130] fp16
#pragma unroll
        for (int f = 0; f < 2; f++) {
            int mb = wm_ * 32 + f * 16 + l4;
            float b0v = bias[m0 + mb], b1v = bias[m0 + mb + 8];
#pragma unroll
            for (int j = 0; j < 8; j++) {
                int nl = wn * 64 + j * 8 + l2;
#pragma unroll
                for (int e = 0; e < 4; e++) {
                    float v = acc[f][j][e] + ((e & 2) ? b1v : b0v);
                    v = fmaxf(v, 0.f);
                    sH[(nl + (e & 1)) * 130 + mb + ((e & 2) ? 8 : 0)] =
                        __half_as_ushort(__float2half(v));
                }
            }
        }
        __syncthreads();
#pragma unroll 8
        for (int t = 0; t < 64; t++) {
            int idx = tid + t * 256;
            int row = idx >> 7, ml = idx & 127;
            int ng = n0 + row;
            size_t pixpad = (size_t)(((ng >> 8) + 2) * PADW + (ng & 255) + 2) * 256 + m0 + ml;
            g_H[pixpad] = sH[row * 130 + ml];
        }
    } else {
        float* sF = (float*)smem;   // [m 128][pitch 130]
#pragma unroll
        for (int f = 0; f < 2; f++) {
            int mb = wm_ * 32 + f * 16 + l4;
            float b0v = bias[m0 + mb], b1v = bias[m0 + mb + 8];
#pragma unroll
            for (int j = 0; j < 8; j++) {
                int nl = wn * 64 + j * 8 + l2;
#pragma unroll
                for (int e = 0; e < 4; e++) {
                    float v = acc[f][j][e] + ((e & 2) ? b1v : b0v);
                    sF[(mb + ((e & 2) ? 8 : 0)) * 130 + nl + (e & 1)] = fmaxf(v, 0.f);
                }
            }
        }
        __syncthreads();
#pragma unroll 8
        for (int t = 0; t < 64; t++) {
            int idx = tid + t * 256;
            int ml = idx >> 7, nl = idx & 127;
            Out[(size_t)(m0 + ml) * P2 + n0 + nl] = sF[ml * 130 + nl];
        }
        // ---- fused mask-head partial: sum over this CTA's 128 channels ----
        {
            float* sPart = (float*)(smem + 66560);  // [2][128]
            int nl = tid & 127, half = tid >> 7;
            float s = 0.f;
#pragma unroll 16
            for (int mlh = 0; mlh < 64; mlh++) {
                int ml = half * 64 + mlh;
                s += wm[m0 + ml] * sF[ml * 130 + nl];
            }
            sPart[half * 128 + nl] = s;
            __syncthreads();
            if (tid < 128)
                g_MaskPart[(size_t)blockIdx.y * P2 + n0 + tid] =
                    sPart[tid] + sPart[128 + tid];
        }
    }
}

// -------------------- conv2: fp16 1-term, B reused across dx ---------------
__global__ void __launch_bounds__(256, 2) k_conv2mma(const float* __restrict__ bias2)
{
    extern __shared__ __align__(1024) char smem[];
    uint32_t sb = smem_u32(smem);
    const int tid = threadIdx.x;
    const int lane = tid & 31, wid = tid >> 5;
    const int wm = wid >> 1, wn = wid & 1;
    const int bx = blockIdx.x;
    const int y = bx >> 1, x0 = (bx & 1) * 128;
    const int m0 = blockIdx.y * 128;
    const int pixbase = y * 256 + x0;

    const int rb = tid >> 3;
    const int cc = tid & 7;
    const char* WtB = (const char*)g_Wt;
    const char* HB  = (const char*)g_H;

    uint32_t aRow[2], aSw[2];
    const uint32_t aHi = lane >> 4;
#pragma unroll
    for (int f = 0; f < 2; f++) {
        int r = wm * 32 + f * 16 + (lane & 15);
        aRow[f] = r << 7;
        aSw[f] = r & 7;
    }
    uint32_t rB0[4];
    const uint32_t bHi = (lane >> 3) & 1;
#pragma unroll
    for (int g = 0; g < 4; g++)
        rB0[g] = wn * 64 + g * 16 + (lane & 7) + ((lane >> 4) << 3);

    float acc[2][8][4];
#pragma unroll
    for (int i = 0; i < 2; i++)
#pragma unroll
        for (int j = 0; j < 8; j++)
#pragma unroll
            for (int e = 0; e < 4; e++) acc[i][j][e] = 0.f;

    auto fill = [&](int it) {
        int dy = it / 20, rem = it % 20, chunk = rem / 5, dx = rem % 5;
        int tap = dy * 5 + dx;
        const char* srcA = WtB + (long)tap * 131072 + chunk * 128;
        uint32_t stgA = sb + (it % 3) * C2_A_STAGE;
#pragma unroll
        for (int t = 0; t < 4; t++) {
            int r = rb + 32 * t;
            uint32_t sw = (uint32_t)((cc ^ (r & 7)) << 4);
            long a0 = (long)(m0 + r) * 512 + cc * 16;
            cpa16(stgA + r * 128 + sw, srcA + a0);
        }
        if (dx == 0) {
            uint32_t stgB = sb + C2_B_OFF + ((it / 5) & 1) * C2_B_SLOT;
            const char* srcB = HB + (long)((y + dy) * PADW + x0) * 512 + chunk * 128;
            for (int o = tid * 16; o < C2_B_SLOT; o += 4096) {
                int r = o >> 7;
                int cB = o & 127;
                uint32_t sw = (uint32_t)(r * 128 + (cB ^ ((r & 7) << 4)));
                cpa16(stgB + sw, srcB + (long)r * 512 + cB);
            }
        }
        asm volatile("cp.async.commit_group;" ::: "memory");
    };

    fill(0);
    fill(1);

    for (int it = 0; it < 100; it++) {
        if (it == 99) asm volatile("cp.async.wait_group 0;" ::: "memory");
        else          asm volatile("cp.async.wait_group 1;" ::: "memory");
        __syncthreads();
        const int dxi = it % 5;
        uint32_t stgA = sb + (it % 3) * C2_A_STAGE;
        uint32_t stgB = sb + C2_B_OFF + ((it / 5) & 1) * C2_B_SLOT;
#pragma unroll
        for (int ks = 0; ks < 4; ks++) {
            uint32_t Wh[2][4], Bh[4][4];
#pragma unroll
            for (int f = 0; f < 2; f++) {
                uint32_t col = ((((uint32_t)(ks << 1) + aHi) ^ aSw[f]) << 4);
                ldsm4(Wh[f], stgA + aRow[f] + col);
            }
#pragma unroll
            for (int g = 0; g < 4; g++) {
                uint32_t rr = rB0[g] + dxi;
                uint32_t addr = stgB + (rr << 7)
                              + ((((uint32_t)(ks << 1) + bHi) ^ (rr & 7)) << 4);
                ldsm4(Bh[g], addr);
            }
#pragma unroll
            for (int f = 0; f < 2; f++)
#pragma unroll
                for (int g = 0; g < 4; g++)
#pragma unroll
                    for (int h = 0; h < 2; h++)
                        mma_f16(acc[f][g * 2 + h], Wh[f],
                                Bh[g][h * 2], Bh[g][h * 2 + 1]);
        }
        if (it + 2 < 100) fill(it + 2);
    }
    __syncthreads();

    // staged epilogue -> g_Ct fp16 px-major, coalesced
    const int l4 = lane >> 2, l2 = (lane & 3) * 2;
    unsigned short* sH = (unsigned short*)smem;   // [n 128][pitch 130]
#pragma unroll
    for (int f = 0; f < 2; f++) {
        int mb = wm * 32 + f * 16 + l4;
        float b0v = bias2[m0 + mb], b1v = bias2[m0 + mb + 8];
#pragma unroll
        for (int j = 0; j < 8; j++) {
            int nl = wn * 64 + j * 8 + l2;
#pragma unroll
            for (int e = 0; e < 4; e++) {
                float v = acc[f][j][e] + ((e & 2) ? b1v : b0v);
                sH[(nl + (e & 1)) * 130 + mb + ((e & 2) ? 8 : 0)] =
                    __half_as_ushort(__float2half(fmaxf(v, 0.f)));
            }
        }
    }
    __syncthreads();
#pragma unroll 8
    for (int t = 0; t < 64; t++) {
        int idx = tid + t * 256;
        int row = idx >> 7, ml = idx & 127;
        g_Ct[(size_t)(pixbase + row) * 256 + m0 + ml] =
            __ushort_as_half(sH[row * 130 + ml]);
    }
}

// -------------------- guided filter (px-major, wide kernels) ---------------
__global__ void k_gf_row1()
{
    int idx = blockIdx.x * blockDim.x + threadIdx.x;
    if (idx >= CE * P2) return;
    int c = idx & 255;
    int pp = idx >> 8;
    int y = pp >> 8, x = pp & 255;
    size_t rowbase = (size_t)(y * 256) * 256 + c;
    float sp = 0.f, sip = 0.f;
    for (int dxx = -2; dxx <= 2; dxx++) {
        int xx = x + dxx;
        if (xx < 0 || xx > 255) continue;
        float pv = __half2float(g_Ct[rowbase + (size_t)xx * 256]);
        sp  += pv;
        sip += pv * g_guide[y * 256 + xx];
    }
    g_D[idx] = __float2half(sp);
    g_E[idx] = sip;
}

__global__ void k_gf_col1()
{
    int idx = blockIdx.x * blockDim.x + threadIdx.x;
    if (idx >= CE * P2) return;
    int pp = idx >> 8;
    int y = pp >> 8, x = pp & 255;
    float sp = 0.f, sip = 0.f;
    for (int dyy = -2; dyy <= 2; dyy++) {
        int yy = y + dyy;
        if (yy < 0 || yy > 255) continue;
        int off = idx + (dyy << 16);
        sp  += __half2float(g_D[off]);
        sip += g_E[off];
    }
    float inv = 1.f / (float)(cnt_axis(y) * cnt_axis(x));
    float mp  = sp * inv;
    float mIp = sip * inv;
    float mI  = g_meanI[pp];
    float a = (mIp - mI * mp) / (g_varI[pp] + EPS_GF);
    g_Aa[idx] = __float2half(a);
    g_F[idx]  = __float2half(mp - a * mI);
}

__global__ void k_gf_row2()
{
    int idx = blockIdx.x * blockDim.x + threadIdx.x;
    if (idx >= CE * P2) return;
    int c = idx & 255;
    int pp = idx >> 8;
    int y = pp >> 8, x = pp & 255;
    size_t rowbase = (size_t)(y * 256) * 256 + c;
    float sa = 0.f, sb = 0.f;
    for (int dxx = -2; dxx <= 2; dxx++) {
        int xx = x + dxx;
        if (xx < 0 || xx > 255) continue;
        sa += __half2float(g_Aa[rowbase + (size_t)xx * 256]);
        sb += __half2float(g_F [rowbase + (size_t)xx * 256]);
    }
    g_D[idx]  = __float2half(sa);
    g_Eh[idx] = __float2half(sb);
}

// col2 emits filt directly as fp16 into g_V (conv3 input)
__global__ void k_gf_col2()
{
    int idx = blockIdx.x * blockDim.x + threadIdx.x;
    if (idx >= CE * P2) return;
    int pp = idx >> 8;
    int y = pp >> 8, x = pp & 255;
    float sa = 0.f, sb = 0.f;
    for (int dyy = -2; dyy <= 2; dyy++) {
        int yy = y + dyy;
        if (yy < 0 || yy > 255) continue;
        int off = idx + (dyy << 16);
        sa += __half2float(g_D[off]);
        sb += __half2float(g_Eh[off]);
    }
    float inv = 1.f / (float)(cnt_axis(y) * cnt_axis(x));
    float filt = (sa * inv) * g_guide[pp] + sb * inv;
    g_V[idx] = __float2half(filt);
}

// -------------------- mask head combine ------------------------------------
__global__ void k_maskhead(const float* __restrict__ bm,
                           float* __restrict__ maskOut)
{
    int p = blockIdx.x * blockDim.x + threadIdx.x;
    if (p >= P2) return;
    float s = g_MaskPart[p] + g_MaskPart[P2 + p] + bm[0];
    maskOut[p] = 1.f / (1.f + expf(-s));
}

// ---------------------------------------------------------------------------
extern "C" void kernel_launch(void* const* d_in, const int* in_sizes, int n_in,
                              void* d_out, int out_size)
{
    const float* fg   = (const float*)d_in[0];
    const float* bg   = (const float*)d_in[1];
    const float* mask = (const float*)d_in[2];
    const float* feat = (const float*)d_in[3];
    const float* w1   = (const float*)d_in[4];
    const float* b1   = (const float*)d_in[5];
    const float* w2   = (const float*)d_in[6];
    const float* b2   = (const float*)d_in[7];
    const float* w3   = (const float*)d_in[8];
    const float* b3   = (const float*)d_in[9];
    const float* wm   = (const float*)d_in[10];
    const float* bm   = (const float*)d_in[11];

    float* out     = (float*)d_out;
    float* maskOut = out;           // (1,1,256,256)
    float* featOut = out + P2;      // (1,256,256,256)

    const int T = 256;

    cudaFuncSetAttribute(k_conv2mma,
                         cudaFuncAttributeMaxDynamicSharedMemorySize, SMEM_C2);
    cudaFuncSetAttribute(k_mma1x1<5, 0>,
                         cudaFuncAttributeMaxDynamicSharedMemorySize, SMEM_1X1);
    cudaFuncSetAttribute(k_mma1x1<4, 1>,
                         cudaFuncAttributeMaxDynamicSharedMemorySize, SMEM_1X1);

    // weight preps (no deps)
    k_prepw <<<(WT_ELEMS + T - 1) / T, T>>>(w2);
    k_prepw1<<<(256 * K1PAD + T - 1) / T, T>>>(w1);
    k_prepw3<<<(256 * 256 + T - 1) / T, T>>>(w3);
    // 1. fused upsample + transpose + guide -> g_U fp16, g_guide
    k_upT<<<dim3(P2 / 32, K1PAD / 32), dim3(32, 8)>>>(fg, bg, mask, feat);
    // 2. box statistics of guide
    k_istats<<<(P2 + T - 1) / T, T>>>();
    // 3. conv1 mma -> g_H (fp16 single plane)
    k_mma1x1<5, 0><<<dim3(512, 2), 256, SMEM_1X1>>>(b1, nullptr, nullptr);
    // 4. conv2 mma (fp16 1-term) -> g_Ct fp16
    k_conv2mma<<<dim3(512, 2), 256, SMEM_C2>>>(b2);
    // 5. guided filter (fp16 storage, E fp32); col2 writes g_V fp16
    int NB = (CE * P2 + T - 1) / T;
    k_gf_row1<<<NB, T>>>();
    k_gf_col1<<<NB, T>>>();
    k_gf_row2<<<NB, T>>>();
    k_gf_col2<<<NB, T>>>();
    // 6. conv3 mma -> featOut + fused mask partials
    k_mma1x1<4, 1><<<dim3(512, 2), 256, SMEM_1X1>>>(b3, wm, featOut);
    // 7. mask head combine (sigmoid)
    k_maskhead<<<(P2 + T - 1) / T, T>>>(bm, maskOut);
}

// round 17
// speedup vs baseline: 2.5146x; 1.1592x over previous
#include <cuda_runtime.h>
#include <cuda_bf16.h>
#include <cuda_fp16.h>
#include <math.h>
#include <stdint.h>

// ---------------------------------------------------------------------------
// GuidedUpsampleUnitGF — single-term fp16 mma convs; GF vectorized + fused
//   (E = I*p sums fp32: cancellation-sensitive)
// NOTE: __device__ globals must NEVER be passed as kernel args from host.
// ---------------------------------------------------------------------------

#define P2    65536
#define C_IN  263
#define CE    256
#define EPS_GF 0.01f

#define PADH 260
#define PADW 264
#define PADP (PADH * PADW)
#define HPLANE ((size_t)PADP * 256)

#define WT_ELEMS (25 * 256 * 256)
#define W1_ELEMS (256 * 320)
#define W3_ELEMS (256 * 256)

#define K1PAD 320
#define UPLANE ((size_t)P2 * K1PAD)
#define VPLANE ((size_t)P2 * 256)

#define STAGE_1X1 32768
#define SMEM_1X1 (3 * STAGE_1X1)

#define C2_A_STAGE 16384
#define C2_B_OFF   49152
#define C2_B_SLOT  16896
#define SMEM_C2    (C2_B_OFF + 2 * C2_B_SLOT)

// -------------------- scratch ----------------------------------------------
__device__ __align__(256) __half g_Ct[(size_t)P2 * 256]; // px-major conv2 out
__device__ __align__(256) __half g_Aa[(size_t)P2 * 256]; // rowsum(a)
__device__ __align__(256) __half g_D [(size_t)P2 * 256]; // p-rowsums
__device__ __align__(256) float  g_E [(size_t)P2 * 256]; // I*p rowsums (fp32!)
__device__ __align__(256) __half g_F [(size_t)P2 * 256]; // rowsum(b)
__device__ __align__(256) float g_guide[P2];
__device__ __align__(256) float g_meanI[P2];
__device__ __align__(256) float g_varI[P2];
__device__ __align__(256) float g_MaskPart[2 * P2];
__device__ __align__(256) unsigned short g_H[HPLANE];
__device__ __align__(256) __half g_Wt[WT_ELEMS];
__device__ __align__(256) __half g_U [UPLANE];
__device__ __align__(256) __half g_V [VPLANE];
__device__ __align__(256) __half g_W1[W1_ELEMS];
__device__ __align__(256) __half g_W3[W3_ELEMS];

// -------------------- helpers ----------------------------------------------
__device__ __forceinline__ uint32_t smem_u32(const void* p) {
    uint32_t a;
    asm("{ .reg .u64 t; cvta.to.shared.u64 t, %1; cvt.u32.u64 %0, t; }" : "=r"(a) : "l"(p));
    return a;
}
__device__ __forceinline__ void cpa16(uint32_t dst, const void* src) {
    asm volatile("cp.async.cg.shared.global [%0], [%1], 16;\n" :: "r"(dst), "l"(src));
}
__device__ __forceinline__ void ldsm4(uint32_t* r, uint32_t addr) {
    asm volatile("ldmatrix.sync.aligned.m8n8.x4.shared.b16 {%0,%1,%2,%3}, [%4];"
                 : "=r"(r[0]), "=r"(r[1]), "=r"(r[2]), "=r"(r[3]) : "r"(addr));
}
__device__ __forceinline__ void mma_f16(float* d, const uint32_t* a,
                                        uint32_t b0, uint32_t b1) {
    asm volatile("mma.sync.aligned.m16n8k16.row.col.f32.f16.f16.f32 "
                 "{%0,%1,%2,%3}, {%4,%5,%6,%7}, {%8,%9}, {%0,%1,%2,%3};"
                 : "+f"(d[0]), "+f"(d[1]), "+f"(d[2]), "+f"(d[3])
                 : "r"(a[0]), "r"(a[1]), "r"(a[2]), "r"(a[3]), "r"(b0), "r"(b1));
}

// -------------------- fused upsample + transpose + guide -> g_U fp16 --------
__global__ void __launch_bounds__(256) k_upT(const float* __restrict__ fg,
                                             const float* __restrict__ bg,
                                             const float* __restrict__ mask,
                                             const float* __restrict__ feat)
{
    __shared__ float tile[32][33];
    const int p0 = blockIdx.x * 32;
    const int c0 = blockIdx.y * 32;
    const int tx = threadIdx.x, ty = threadIdx.y;

    int p = p0 + tx;
    int y = p >> 8, x = p & 255;
    float sy = 0.5f * (float)y - 0.25f;
    float sx = 0.5f * (float)x - 0.25f;
    float fy = sy - floorf(sy);
    float fx = sx - floorf(sx);
    int y0 = (int)floorf(sy);
    int x0 = (int)floorf(sx);
    int y0c = max(y0, 0),       x0c = max(x0, 0);
    int y1c = min(y0 + 1, 127), x1c = min(x0 + 1, 127);
    int i00 = y0c * 128 + x0c, i01 = y0c * 128 + x1c;
    int i10 = y1c * 128 + x0c, i11 = y1c * 128 + x1c;
    float w00 = (1.f - fy) * (1.f - fx), w01 = (1.f - fy) * fx;
    float w10 = fy * (1.f - fx),         w11 = fy * fx;

#pragma unroll
    for (int k = 0; k < 4; k++) {
        int ch = c0 + ty + k * 8;
        float v = 0.f;
        if (ch < C_IN) {
            const float* src;
            if (ch == 0)      src = mask;
            else if (ch <= 3) src = fg + (ch - 1) * 16384;
            else if (ch <= 6) src = bg + (ch - 4) * 16384;
            else              src = feat + (ch - 7) * 16384;
            v = w00 * src[i00] + w01 * src[i01] + w10 * src[i10] + w11 * src[i11];
        }
        tile[ty + k * 8][tx] = v;
    }
    __syncthreads();
    if (c0 == 0 && ty == 0)
        g_guide[p0 + tx] = (tile[1][tx] + tile[2][tx] + tile[3][tx]) * (128.0f / 3.0f);
#pragma unroll
    for (int k = 0; k < 4; k++) {
        int pp = p0 + ty + k * 8;
        int ch = c0 + tx;
        g_U[(size_t)pp * K1PAD + ch] = __float2half(tile[tx][ty + k * 8]);
    }
}

__device__ __forceinline__ int cnt_axis(int i)
{
    return min(i + 2, 255) - max(i - 2, 0) + 1;
}

__global__ void k_istats()
{
    int p = blockIdx.x * blockDim.x + threadIdx.x;
    if (p >= P2) return;
    int y = p >> 8, x = p & 255;
    float sI = 0.f, sI2 = 0.f;
    for (int dy = -2; dy <= 2; dy++) {
        int yy = y + dy;
        if (yy < 0 || yy > 255) continue;
        for (int dx = -2; dx <= 2; dx++) {
            int xx = x + dx;
            if (xx < 0 || xx > 255) continue;
            float v = g_guide[yy * 256 + xx];
            sI += v; sI2 += v * v;
        }
    }
    float inv = 1.f / (float)(cnt_axis(y) * cnt_axis(x));
    float mI = sI * inv;
    g_meanI[p] = mI;
    g_varI[p]  = sI2 * inv - mI * mI;
}

// -------------------- merged weight prep (all fp16 single planes) -----------
__global__ void k_prepall(const float* __restrict__ w2,
                          const float* __restrict__ w1,
                          const float* __restrict__ w3)
{
    int idx = blockIdx.x * blockDim.x + threadIdx.x;
    if (idx < WT_ELEMS) {
        int ch = idx & 255;
        int m  = (idx >> 8) & 255;
        int tap = idx >> 16;
        g_Wt[idx] = __float2half(w2[(size_t)m * 6400 + ch * 25 + tap]);
        return;
    }
    idx -= WT_ELEMS;
    if (idx < W1_ELEMS) {
        int ch = idx % K1PAD;
        int m  = idx / K1PAD;
        g_W1[idx] = __float2half((ch < C_IN) ? w1[(size_t)m * C_IN + ch] : 0.f);
        return;
    }
    idx -= W1_ELEMS;
    if (idx < W3_ELEMS)
        g_W3[idx] = __float2half(w3[idx]);
}

// -------------------- generic 1x1 conv MMA (fp16 1-term) --------------------
template<int NKC, int MODE>
__global__ void __launch_bounds__(256, 2) k_mma1x1(const float* __restrict__ bias,
                                                   const float* __restrict__ wm,
                                                   float* __restrict__ Out)
{
    constexpr int KPAD = NKC * 64;

    extern __shared__ __align__(1024) char smem[];
    uint32_t sb = smem_u32(smem);
    const int tid = threadIdx.x;
    const int lane = tid & 31, wid = tid >> 5;
    const int wm_ = wid >> 1, wn = wid & 1;
    const int n0 = blockIdx.x * 128;
    const int m0 = blockIdx.y * 128;

    const int rb = tid >> 3;
    const int cc = tid & 7;
    const char* AB = (MODE == 0) ? (const char*)g_W1 : (const char*)g_W3;
    const char* BB = (MODE == 0) ? (const char*)g_U  : (const char*)g_V;

    uint32_t aRow[2], aSw[2];
    const uint32_t aHi = lane >> 4;
#pragma unroll
    for (int f = 0; f < 2; f++) {
        int r = wm_ * 32 + f * 16 + (lane & 15);
        aRow[f] = r << 7;
        aSw[f] = r & 7;
    }
    uint32_t bRow[4], bSw[4];
    const uint32_t bHi = (lane >> 3) & 1;
#pragma unroll
    for (int g = 0; g < 4; g++) {
        int r = wn * 64 + g * 16 + (lane & 7) + ((lane >> 4) << 3);
        bRow[g] = r << 7;
        bSw[g] = r & 7;
    }

    float acc[2][8][4];
#pragma unroll
    for (int i = 0; i < 2; i++)
#pragma unroll
        for (int j = 0; j < 8; j++)
#pragma unroll
            for (int e = 0; e < 4; e++) acc[i][j][e] = 0.f;

    auto fill = [&](int it) {
        uint32_t stg = sb + (it % 3) * STAGE_1X1;
        long kO = (long)it * 128;
#pragma unroll
        for (int t = 0; t < 4; t++) {
            int r = rb + 32 * t;
            uint32_t sw = (uint32_t)((cc ^ (r & 7)) << 4);
            long a0 = (long)(m0 + r) * (KPAD * 2) + kO + cc * 16;
            cpa16(stg + r * 128 + sw, AB + a0);
            long b0 = (long)(n0 + r) * (KPAD * 2) + kO + cc * 16;
            cpa16(stg + 16384 + r * 128 + sw, BB + b0);
        }
        asm volatile("cp.async.commit_group;" ::: "memory");
    };

    fill(0);
    fill(1);

    for (int it = 0; it < NKC; it++) {
        if (it == NKC - 1) asm volatile("cp.async.wait_group 0;" ::: "memory");
        else               asm volatile("cp.async.wait_group 1;" ::: "memory");
        __syncthreads();
        uint32_t stg = sb + (it % 3) * STAGE_1X1;
#pragma unroll
        for (int ks = 0; ks < 4; ks++) {
            uint32_t Wh[2][4], Bh[4][4];
#pragma unroll
            for (int f = 0; f < 2; f++) {
                uint32_t col = ((((uint32_t)(ks << 1) + aHi) ^ aSw[f]) << 4);
                ldsm4(Wh[f], stg + aRow[f] + col);
            }
#pragma unroll
            for (int g = 0; g < 4; g++) {
                uint32_t col = ((((uint32_t)(ks << 1) + bHi) ^ bSw[g]) << 4);
                ldsm4(Bh[g], stg + 16384 + bRow[g] + col);
            }
#pragma unroll
            for (int f = 0; f < 2; f++)
#pragma unroll
                for (int g = 0; g < 4; g++)
#pragma unroll
                    for (int h = 0; h < 2; h++)
                        mma_f16(acc[f][g * 2 + h], Wh[f],
                                Bh[g][h * 2], Bh[g][h * 2 + 1]);
        }
        if (it + 2 < NKC) fill(it + 2);
    }
    __syncthreads();

    // ---- staged epilogue ----
    const int l4 = lane >> 2, l2 = (lane & 3) * 2;
    if (MODE == 0) {
        unsigned short* sH = (unsigned short*)smem;
#pragma unroll
        for (int f = 0; f < 2; f++) {
            int mb = wm_ * 32 + f * 16 + l4;
            float b0v = bias[m0 + mb], b1v = bias[m0 + mb + 8];
#pragma unroll
            for (int j = 0; j < 8; j++) {
                int nl = wn * 64 + j * 8 + l2;
#pragma unroll
                for (int e = 0; e < 4; e++) {
                    float v = acc[f][j][e] + ((e & 2) ? b1v : b0v);
                    v = fmaxf(v, 0.f);
                    sH[(nl + (e & 1)) * 130 + mb + ((e & 2) ? 8 : 0)] =
                        __half_as_ushort(__float2half(v));
                }
            }
        }
        __syncthreads();
#pragma unroll 8
        for (int t = 0; t < 64; t++) {
            int idx = tid + t * 256;
            int row = idx >> 7, ml = idx & 127;
            int ng = n0 + row;
            size_t pixpad = (size_t)(((ng >> 8) + 2) * PADW + (ng & 255) + 2) * 256 + m0 + ml;
            g_H[pixpad] = sH[row * 130 + ml];
        }
    } else {
        float* sF = (float*)smem;
#pragma unroll
        for (int f = 0; f < 2; f++) {
            int mb = wm_ * 32 + f * 16 + l4;
            float b0v = bias[m0 + mb], b1v = bias[m0 + mb + 8];
#pragma unroll
            for (int j = 0; j < 8; j++) {
                int nl = wn * 64 + j * 8 + l2;
#pragma unroll
                for (int e = 0; e < 4; e++) {
                    float v = acc[f][j][e] + ((e & 2) ? b1v : b0v);
                    sF[(mb + ((e & 2) ? 8 : 0)) * 130 + nl + (e & 1)] = fmaxf(v, 0.f);
                }
            }
        }
        __syncthreads();
#pragma unroll 8
        for (int t = 0; t < 64; t++) {
            int idx = tid + t * 256;
            int ml = idx >> 7, nl = idx & 127;
            Out[(size_t)(m0 + ml) * P2 + n0 + nl] = sF[ml * 130 + nl];
        }
        {
            float* sPart = (float*)(smem + 66560);
            int nl = tid & 127, half = tid >> 7;
            float s = 0.f;
#pragma unroll 16
            for (int mlh = 0; mlh < 64; mlh++) {
                int ml = half * 64 + mlh;
                s += wm[m0 + ml] * sF[ml * 130 + nl];
            }
            sPart[half * 128 + nl] = s;
            __syncthreads();
            if (tid < 128)
                g_MaskPart[(size_t)blockIdx.y * P2 + n0 + tid] =
                    sPart[tid] + sPart[128 + tid];
        }
    }
}

// -------------------- conv2: fp16 1-term, B reused across dx ---------------
__global__ void __launch_bounds__(256, 2) k_conv2mma(const float* __restrict__ bias2)
{
    extern __shared__ __align__(1024) char smem[];
    uint32_t sb = smem_u32(smem);
    const int tid = threadIdx.x;
    const int lane = tid & 31, wid = tid >> 5;
    const int wm = wid >> 1, wn = wid & 1;
    const int bx = blockIdx.x;
    const int y = bx >> 1, x0 = (bx & 1) * 128;
    const int m0 = blockIdx.y * 128;
    const int pixbase = y * 256 + x0;

    const int rb = tid >> 3;
    const int cc = tid & 7;
    const char* WtB = (const char*)g_Wt;
    const char* HB  = (const char*)g_H;

    uint32_t aRow[2], aSw[2];
    const uint32_t aHi = lane >> 4;
#pragma unroll
    for (int f = 0; f < 2; f++) {
        int r = wm * 32 + f * 16 + (lane & 15);
        aRow[f] = r << 7;
        aSw[f] = r & 7;
    }
    uint32_t rB0[4];
    const uint32_t bHi = (lane >> 3) & 1;
#pragma unroll
    for (int g = 0; g < 4; g++)
        rB0[g] = wn * 64 + g * 16 + (lane & 7) + ((lane >> 4) << 3);

    float acc[2][8][4];
#pragma unroll
    for (int i = 0; i < 2; i++)
#pragma unroll
        for (int j = 0; j < 8; j++)
#pragma unroll
            for (int e = 0; e < 4; e++) acc[i][j][e] = 0.f;

    auto fill = [&](int it) {
        int dy = it / 20, rem = it % 20, chunk = rem / 5, dx = rem % 5;
        int tap = dy * 5 + dx;
        const char* srcA = WtB + (long)tap * 131072 + chunk * 128;
        uint32_t stgA = sb + (it % 3) * C2_A_STAGE;
#pragma unroll
        for (int t = 0; t < 4; t++) {
            int r = rb + 32 * t;
            uint32_t sw = (uint32_t)((cc ^ (r & 7)) << 4);
            long a0 = (long)(m0 + r) * 512 + cc * 16;
            cpa16(stgA + r * 128 + sw, srcA + a0);
        }
        if (dx == 0) {
            uint32_t stgB = sb + C2_B_OFF + ((it / 5) & 1) * C2_B_SLOT;
            const char* srcB = HB + (long)((y + dy) * PADW + x0) * 512 + chunk * 128;
            for (int o = tid * 16; o < C2_B_SLOT; o += 4096) {
                int r = o >> 7;
                int cB = o & 127;
                uint32_t sw = (uint32_t)(r * 128 + (cB ^ ((r & 7) << 4)));
                cpa16(stgB + sw, srcB + (long)r * 512 + cB);
            }
        }
        asm volatile("cp.async.commit_group;" ::: "memory");
    };

    fill(0);
    fill(1);

    for (int it = 0; it < 100; it++) {
        if (it == 99) asm volatile("cp.async.wait_group 0;" ::: "memory");
        else          asm volatile("cp.async.wait_group 1;" ::: "memory");
        __syncthreads();
        const int dxi = it % 5;
        uint32_t stgA = sb + (it % 3) * C2_A_STAGE;
        uint32_t stgB = sb + C2_B_OFF + ((it / 5) & 1) * C2_B_SLOT;
#pragma unroll
        for (int ks = 0; ks < 4; ks++) {
            uint32_t Wh[2][4], Bh[4][4];
#pragma unroll
            for (int f = 0; f < 2; f++) {
                uint32_t col = ((((uint32_t)(ks << 1) + aHi) ^ aSw[f]) << 4);
                ldsm4(Wh[f], stgA + aRow[f] + col);
            }
#pragma unroll
            for (int g = 0; g < 4; g++) {
                uint32_t rr = rB0[g] + dxi;
                uint32_t addr = stgB + (rr << 7)
                              + ((((uint32_t)(ks << 1) + bHi) ^ (rr & 7)) << 4);
                ldsm4(Bh[g], addr);
            }
#pragma unroll
            for (int f = 0; f < 2; f++)
#pragma unroll
                for (int g = 0; g < 4; g++)
#pragma unroll
                    for (int h = 0; h < 2; h++)
                        mma_f16(acc[f][g * 2 + h], Wh[f],
                                Bh[g][h * 2], Bh[g][h * 2 + 1]);
        }
        if (it + 2 < 100) fill(it + 2);
    }
    __syncthreads();

    const int l4 = lane >> 2, l2 = (lane & 3) * 2;
    unsigned short* sH = (unsigned short*)smem;
#pragma unroll
    for (int f = 0; f < 2; f++) {
        int mb = wm * 32 + f * 16 + l4;
        float b0v = bias2[m0 + mb], b1v = bias2[m0 + mb + 8];
#pragma unroll
        for (int j = 0; j < 8; j++) {
            int nl = wn * 64 + j * 8 + l2;
#pragma unroll
            for (int e = 0; e < 4; e++) {
                float v = acc[f][j][e] + ((e & 2) ? b1v : b0v);
                sH[(nl + (e & 1)) * 130 + mb + ((e & 2) ? 8 : 0)] =
                    __half_as_ushort(__float2half(fmaxf(v, 0.f)));
            }
        }
    }
    __syncthreads();
#pragma unroll 8
    for (int t = 0; t < 64; t++) {
        int idx = tid + t * 256;
        int row = idx >> 7, ml = idx & 127;
        g_Ct[(size_t)(pixbase + row) * 256 + m0 + ml] =
            __ushort_as_half(sH[row * 130 + ml]);
    }
}

// -------------------- guided filter -----------------------------------------
// pass 1 rows (half2): D = rowsum(p), E(f32x2) = rowsum(I*p)
__global__ void __launch_bounds__(256) k_gf_row1()
{
    int idx = blockIdx.x * 256 + threadIdx.x;     // over P2*128 half2 ch
    int c2 = idx & 127;
    int pp = idx >> 7;
    int y = pp >> 8, x = pp & 255;
    const __half2* Ct2 = (const __half2*)g_Ct;
    size_t rowbase = (size_t)(y * 256) * 128 + c2;
    float2 sp = make_float2(0.f, 0.f), sip = make_float2(0.f, 0.f);
    for (int dxx = -2; dxx <= 2; dxx++) {
        int xx = x + dxx;
        if ((unsigned)xx > 255u) continue;
        float2 pv = __half22float2(Ct2[rowbase + (size_t)xx * 128]);
        float gv = g_guide[y * 256 + xx];
        sp.x += pv.x; sp.y += pv.y;
        sip.x += pv.x * gv; sip.y += pv.y * gv;
    }
    ((__half2*)g_D)[idx] = __floats2half2_rn(sp.x, sp.y);
    ((float2*)g_E)[idx] = sip;
}

// fused col1 + row2: per (y, 32ch-group) CTA over all 256 x.
// writes rowsum(a)->g_Aa, rowsum(b)->g_F  (half2)
__global__ void __launch_bounds__(256) k_gf_colrow()
{
    __shared__ __half2 sa [256][17];
    __shared__ __half2 sbv[256][17];
    const int y  = blockIdx.x;
    const int cg = blockIdx.y;            // 8 groups of 16 half2
    const int tid = threadIdx.x;
    const int c2l = tid & 15;
    const int xs  = tid >> 4;             // 16 x-slots
    const int c2  = cg * 16 + c2l;
    const float cy = (float)cnt_axis(y);

#pragma unroll 4
    for (int k = 0; k < 16; k++) {
        int x = xs * 16 + k;
        int pp = y * 256 + x;
        float2 sp = make_float2(0.f, 0.f), sip = make_float2(0.f, 0.f);
#pragma unroll
        for (int dyy = -2; dyy <= 2; dyy++) {
            int yy = y + dyy;
            if ((unsigned)yy > 255u) continue;
            size_t off = (size_t)(yy * 256 + x) * 128 + c2;
            float2 d = __half22float2(((const __half2*)g_D)[off]);
            float2 e = ((const float2*)g_E)[off];
            sp.x += d.x; sp.y += d.y;
            sip.x += e.x; sip.y += e.y;
        }
        float inv = 1.f / (cy * (float)cnt_axis(x));
        float mI = g_meanI[pp];
        float vd = g_varI[pp] + EPS_GF;
        float mpx = sp.x * inv, mpy = sp.y * inv;
        float ax = (sip.x * inv - mI * mpx) / vd;
        float ay = (sip.y * inv - mI * mpy) / vd;
        sa [x][c2l] = __floats2half2_rn(ax, ay);
        sbv[x][c2l] = __floats2half2_rn(mpx - ax * mI, mpy - ay * mI);
    }
    __syncthreads();
#pragma unroll 4
    for (int k = 0; k < 16; k++) {
        int x = xs * 16 + k;
        float2 ra = make_float2(0.f, 0.f), rb = make_float2(0.f, 0.f);
#pragma unroll
        for (int dxx = -2; dxx <= 2; dxx++) {
            int xx = x + dxx;
            if ((unsigned)xx > 255u) continue;
            float2 av = __half22float2(sa [xx][c2l]);
            float2 bv = __half22float2(sbv[xx][c2l]);
            ra.x += av.x; ra.y += av.y;
            rb.x += bv.x; rb.y += bv.y;
        }
        size_t off = (size_t)(y * 256 + x) * 128 + c2;
        ((__half2*)g_Aa)[off] = __floats2half2_rn(ra.x, ra.y);
        ((__half2*)g_F)[off]  = __floats2half2_rn(rb.x, rb.y);
    }
}

// col2 (half2): filt = colmean(rowsum_a)*I + colmean(rowsum_b) -> g_V
__global__ void __launch_bounds__(256) k_gf_col2()
{
    int idx = blockIdx.x * 256 + threadIdx.x;     // over P2*128
    int pp = idx >> 7;
    int y = pp >> 8, x = pp & 255;
    float2 sa = make_float2(0.f, 0.f), sb = make_float2(0.f, 0.f);
    for (int dyy = -2; dyy <= 2; dyy++) {
        int yy = y + dyy;
        if ((unsigned)yy > 255u) continue;
        int off = idx + (dyy << 15);              // 256*128 half2 per y
        float2 av = __half22float2(((const __half2*)g_Aa)[off]);
        float2 bv = __half22float2(((const __half2*)g_F)[off]);
        sa.x += av.x; sa.y += av.y;
        sb.x += bv.x; sb.y += bv.y;
    }
    float inv = 1.f / (float)(cnt_axis(y) * cnt_axis(x));
    float gv = g_guide[pp];
    ((__half2*)g_V)[idx] = __floats2half2_rn(sa.x * inv * gv + sb.x * inv,
                                             sa.y * inv * gv + sb.y * inv);
}

// -------------------- mask head combine ------------------------------------
__global__ void k_maskhead(const float* __restrict__ bm,
                           float* __restrict__ maskOut)
{
    int p = blockIdx.x * blockDim.x + threadIdx.x;
    if (p >= P2) return;
    float s = g_MaskPart[p] + g_MaskPart[P2 + p] + bm[0];
    maskOut[p] = 1.f / (1.f + expf(-s));
}

// ---------------------------------------------------------------------------
extern "C" void kernel_launch(void* const* d_in, const int* in_sizes, int n_in,
                              void* d_out, int out_size)
{
    const float* fg   = (const float*)d_in[0];
    const float* bg   = (const float*)d_in[1];
    const float* mask = (const float*)d_in[2];
    const float* feat = (const float*)d_in[3];
    const float* w1   = (const float*)d_in[4];
    const float* b1   = (const float*)d_in[5];
    const float* w2   = (const float*)d_in[6];
    const float* b2   = (const float*)d_in[7];
    const float* w3   = (const float*)d_in[8];
    const float* b3   = (const float*)d_in[9];
    const float* wm   = (const float*)d_in[10];
    const float* bm   = (const float*)d_in[11];

    float* out     = (float*)d_out;
    float* maskOut = out;           // (1,1,256,256)
    float* featOut = out + P2;      // (1,256,256,256)

    const int T = 256;

    cudaFuncSetAttribute(k_conv2mma,
                         cudaFuncAttributeMaxDynamicSharedMemorySize, SMEM_C2);
    cudaFuncSetAttribute(k_mma1x1<5, 0>,
                         cudaFuncAttributeMaxDynamicSharedMemorySize, SMEM_1X1);
    cudaFuncSetAttribute(k_mma1x1<4, 1>,
                         cudaFuncAttributeMaxDynamicSharedMemorySize, SMEM_1X1);

    // merged weight prep
    const int PREP_N = WT_ELEMS + W1_ELEMS + W3_ELEMS;
    k_prepall<<<(PREP_N + T - 1) / T, T>>>(w2, w1, w3);
    // 1. fused upsample + transpose + guide -> g_U fp16, g_guide
    k_upT<<<dim3(P2 / 32, K1PAD / 32), dim3(32, 8)>>>(fg, bg, mask, feat);
    // 2. box statistics of guide
    k_istats<<<(P2 + T - 1) / T, T>>>();
    // 3. conv1 mma -> g_H (fp16 single plane)
    k_mma1x1<5, 0><<<dim3(512, 2), 256, SMEM_1X1>>>(b1, nullptr, nullptr);
    // 4. conv2 mma -> g_Ct fp16
    k_conv2mma<<<dim3(512, 2), 256, SMEM_C2>>>(b2);
    // 5. guided filter: row1 (vec) -> fused col1+row2 -> col2 (vec, writes g_V)
    k_gf_row1<<<P2 * 128 / T, T>>>();
    k_gf_colrow<<<dim3(256, 8), T>>>();
    k_gf_col2<<<P2 * 128 / T, T>>>();
    // 6. conv3 mma -> featOut + fused mask partials
    k_mma1x1<4, 1><<<dim3(512, 2), 256, SMEM_1X1>>>(b3, wm, featOut);
    // 7. mask head combine
    k_maskhead<<<(P2 + T - 1) / T, T>>>(bm, maskOut);
}